// round 1
// baseline (speedup 1.0000x reference)
#include <cuda_runtime.h>
#include <cuda_bf16.h>
#include <math.h>
#include <stdint.h>

// Problem constants
#define NPTS 8192
#define DIM  512
#define KNN  15
#define NPAIR 105   // 15*14/2

// ---------------- scratch (device globals: no allocation allowed) -------------
__device__ float  g_sqdist[(size_t)NPTS * NPTS];   // 256 MB squared distances
__device__ float  g_norms[NPTS];
__device__ int    g_knni[NPTS * KNN];
__device__ double g_acc[2];                        // [0]=curv sumsq, [1]=ang sumsq

// ---------------- f32x2 packed helpers (sm_103a dual-fp32 pipe) ---------------
typedef unsigned long long u64;
__device__ __forceinline__ u64 pack2(float lo, float hi) {
    u64 r; asm("mov.b64 %0, {%1, %2};" : "=l"(r) : "f"(lo), "f"(hi)); return r;
}
__device__ __forceinline__ u64 fma2(u64 a, u64 b, u64 c) {
    u64 d; asm("fma.rn.f32x2 %0, %1, %2, %3;" : "=l"(d) : "l"(a), "l"(b), "l"(c)); return d;
}
__device__ __forceinline__ void unpack2(u64 v, float& lo, float& hi) {
    asm("mov.b64 {%0, %1}, %2;" : "=f"(lo), "=f"(hi) : "l"(v));
}

// ---------------- kernel 0: zero accumulators ---------------------------------
__global__ void zero_acc_kernel() {
    g_acc[0] = 0.0; g_acc[1] = 0.0;
}

// ---------------- kernel 1: row squared norms ----------------------------------
__global__ void norms_kernel(const float* __restrict__ E) {
    int row  = blockIdx.x * 8 + (threadIdx.x >> 5);
    int lane = threadIdx.x & 31;
    const float4* r = (const float4*)(E + (size_t)row * DIM);
    float s = 0.f;
    #pragma unroll
    for (int c4 = lane; c4 < DIM / 4; c4 += 32) {
        float4 v = r[c4];
        s = fmaf(v.x, v.x, fmaf(v.y, v.y, fmaf(v.z, v.z, fmaf(v.w, v.w, s))));
    }
    #pragma unroll
    for (int o = 16; o; o >>= 1) s += __shfl_xor_sync(0xFFFFFFFFu, s, o);
    if (!lane) g_norms[row] = s;
}

// ---------------- kernel 2: symmetric SGEMM -> squared distances ----------------
// BM=BN=128, BK=16, 256 threads, 8x8 outputs/thread, packed f32x2 FMAs.
// Only tiles with bx<=by computed; result mirrored (matrix symmetric).
__global__ __launch_bounds__(256, 2)
void gemm_sqdist_kernel(const float* __restrict__ E) {
    const int bx = blockIdx.x, by = blockIdx.y;
    if (bx > by) return;

    __shared__ float As[16][128];
    __shared__ float Bs[16][128];

    const int tid  = threadIdx.x;
    const int row0 = by * 128, col0 = bx * 128;

    const int la_r = tid >> 2;           // 0..63
    const int la_c = (tid & 3) * 4;      // 0,4,8,12

    const int ty = tid >> 4;             // 0..15
    const int tx = tid & 15;             // 0..15

    u64 acc[8][4];
    #pragma unroll
    for (int m = 0; m < 8; m++)
        #pragma unroll
        for (int n = 0; n < 4; n++) acc[m][n] = 0ull;

    for (int k0 = 0; k0 < DIM; k0 += 16) {
        #pragma unroll
        for (int rr = 0; rr < 2; rr++) {
            int r = la_r + rr * 64;
            float4 va = *(const float4*)&E[(size_t)(row0 + r) * DIM + k0 + la_c];
            As[la_c + 0][r] = va.x; As[la_c + 1][r] = va.y;
            As[la_c + 2][r] = va.z; As[la_c + 3][r] = va.w;
            float4 vb = *(const float4*)&E[(size_t)(col0 + r) * DIM + k0 + la_c];
            Bs[la_c + 0][r] = vb.x; Bs[la_c + 1][r] = vb.y;
            Bs[la_c + 2][r] = vb.z; Bs[la_c + 3][r] = vb.w;
        }
        __syncthreads();

        #pragma unroll
        for (int k = 0; k < 16; k++) {
            float ra[8];
            u64   rb[4];
            #pragma unroll
            for (int m = 0; m < 8; m++) ra[m] = As[k][ty * 8 + m];
            #pragma unroll
            for (int n = 0; n < 4; n++)
                rb[n] = *(const u64*)&Bs[k][tx * 8 + n * 2];
            #pragma unroll
            for (int m = 0; m < 8; m++) {
                u64 am = pack2(ra[m], ra[m]);
                #pragma unroll
                for (int n = 0; n < 4; n++)
                    acc[m][n] = fma2(am, rb[n], acc[m][n]);
            }
        }
        __syncthreads();
    }

    const float INF = __int_as_float(0x7f800000);
    #pragma unroll
    for (int m = 0; m < 8; m++) {
        int i = row0 + ty * 8 + m;
        float ni = g_norms[i];
        #pragma unroll
        for (int n = 0; n < 4; n++) {
            float d0, d1;
            unpack2(acc[m][n], d0, d1);
            int j0 = col0 + tx * 8 + n * 2;
            int j1 = j0 + 1;
            float s0 = fmaxf(ni + g_norms[j0] - 2.f * d0, 0.f);
            float s1 = fmaxf(ni + g_norms[j1] - 2.f * d1, 0.f);
            if (i == j0) s0 = INF;
            if (i == j1) s1 = INF;
            g_sqdist[(size_t)i * NPTS + j0] = s0;
            g_sqdist[(size_t)i * NPTS + j1] = s1;
            if (bx < by) {
                g_sqdist[(size_t)j0 * NPTS + i] = s0;
                g_sqdist[(size_t)j1 * NPTS + i] = s1;
            }
        }
    }
}

// ---------------- kernel 3: per-row 15-NN + curvature loss ----------------------
__global__ __launch_bounds__(256)
void topk_curv_kernel(const float* __restrict__ ref_curv) {
    const int row = blockIdx.x;
    const int tid = threadIdx.x;
    const float* r = g_sqdist + (size_t)row * NPTS;
    const float INF = __int_as_float(0x7f800000);

    float d[16]; int ix[16];
    #pragma unroll
    for (int q = 0; q < 16; q++) { d[q] = INF; ix[q] = -1; }

    for (int j = tid; j < NPTS; j += 256) {
        float v = r[j];
        if (v < d[15]) {
            float cv = v; int ci = j;
            #pragma unroll
            for (int q = 0; q < 16; q++) {
                if (cv < d[q]) {
                    float tf = d[q]; d[q] = cv; cv = tf;
                    int   ti = ix[q]; ix[q] = ci; ci = ti;
                }
            }
        }
    }

    __shared__ float sd[256 * 16];
    __shared__ int   si[256 * 16];
    #pragma unroll
    for (int q = 0; q < 16; q++) { sd[tid * 16 + q] = d[q]; si[tid * 16 + q] = ix[q]; }
    __syncthreads();

    for (int stride = 128; stride >= 1; stride >>= 1) {
        if (tid < stride) {
            float* A  = &sd[tid * 16];
            float* B  = &sd[(tid + stride) * 16];
            int*   Ai = &si[tid * 16];
            int*   Bi = &si[(tid + stride) * 16];
            float od[16]; int oi[16];
            int pa = 0, pb = 0;
            #pragma unroll
            for (int q = 0; q < 16; q++) {
                float va = A[pa], vb = B[pb];
                if (va <= vb) { od[q] = va; oi[q] = Ai[pa]; pa++; }
                else          { od[q] = vb; oi[q] = Bi[pb]; pb++; }
            }
            #pragma unroll
            for (int q = 0; q < 16; q++) { A[q] = od[q]; Ai[q] = oi[q]; }
        }
        __syncthreads();
    }

    if (tid == 0) {
        float dd[KNN];
        float s = 0.f;
        #pragma unroll
        for (int q = 0; q < KNN; q++) {
            dd[q] = sqrtf(fmaxf(sd[q], 1e-12f));
            s += dd[q];
            g_knni[row * KNN + q] = si[q];
        }
        float mean = s / (float)KNN + 1e-8f;   // EPS_MEAN
        float loss = 0.f;
        #pragma unroll
        for (int q = 0; q < KNN; q++) {
            float sig = dd[q] / mean;          // already sorted ascending
            float df  = sig - ref_curv[row * KNN + q];
            loss = fmaf(df, df, loss);
        }
        atomicAdd(&g_acc[0], (double)loss);
    }
}

// ---------------- kernel 4: angular signature loss ------------------------------
__global__ __launch_bounds__(256)
void angular_kernel(const float* __restrict__ E, const float* __restrict__ ref_ang) {
    const int row  = blockIdx.x;
    const int tid  = threadIdx.x;
    const int lane = tid & 31;
    const int w    = tid >> 5;

    __shared__ float ei[DIM];
    __shared__ float vh[KNN][DIM];
    __shared__ float nrm[KNN];
    __shared__ float cosv[128];
    __shared__ float lsum[8];

    // load center embedding
    if (tid < 128) {
        float4 q = *(const float4*)&E[(size_t)row * DIM + tid * 4];
        *(float4*)&ei[tid * 4] = q;
    }
    if (tid >= 105 && tid < 128) cosv[tid] = __int_as_float(0x7f800000);
    __syncthreads();

    // gather neighbors, form difference vectors, compute norms
    for (int j = w; j < KNN; j += 8) {
        int nb = g_knni[row * KNN + j];
        const float4* src = (const float4*)&E[(size_t)nb * DIM];
        float s = 0.f;
        for (int c4 = lane; c4 < DIM / 4; c4 += 32) {
            float4 q = src[c4];
            float4 e = *(const float4*)&ei[c4 * 4];
            float4 v; v.x = q.x - e.x; v.y = q.y - e.y; v.z = q.z - e.z; v.w = q.w - e.w;
            *(float4*)&vh[j][c4 * 4] = v;
            s = fmaf(v.x, v.x, fmaf(v.y, v.y, fmaf(v.z, v.z, fmaf(v.w, v.w, s))));
        }
        #pragma unroll
        for (int o = 16; o; o >>= 1) s += __shfl_xor_sync(0xFFFFFFFFu, s, o);
        if (!lane) nrm[j] = fmaxf(sqrtf(s), 1e-8f);   // EPS_NORM
    }
    __syncthreads();

    // 105 pairwise cosines
    for (int p = w; p < NPAIR; p += 8) {
        int jj = 0, rem = p;
        while (rem >= (KNN - 1) - jj) { rem -= (KNN - 1) - jj; jj++; }
        int kk = jj + 1 + rem;
        float s = 0.f;
        for (int c = lane; c < DIM; c += 32)
            s = fmaf(vh[jj][c], vh[kk][c], s);
        #pragma unroll
        for (int o = 16; o; o >>= 1) s += __shfl_xor_sync(0xFFFFFFFFu, s, o);
        if (!lane) cosv[p] = s / (nrm[jj] * nrm[kk]);
    }
    __syncthreads();

    // bitonic sort of 128 (105 real + INF padding), ascending
    for (int k = 2; k <= 128; k <<= 1) {
        for (int j2 = k >> 1; j2 > 0; j2 >>= 1) {
            if (tid < 128) {
                int ixj = tid ^ j2;
                if (ixj > tid) {
                    float a = cosv[tid], b = cosv[ixj];
                    bool up = ((tid & k) == 0);
                    if ((a > b) == up) { cosv[tid] = b; cosv[ixj] = a; }
                }
            }
            __syncthreads();
        }
    }

    float s = 0.f;
    for (int t = tid; t < NPAIR; t += 256) {
        float df = cosv[t] - ref_ang[(size_t)row * NPAIR + t];
        s = fmaf(df, df, s);
    }
    #pragma unroll
    for (int o = 16; o; o >>= 1) s += __shfl_xor_sync(0xFFFFFFFFu, s, o);
    if (!lane) lsum[w] = s;
    __syncthreads();
    if (tid == 0) {
        float t = 0.f;
        #pragma unroll
        for (int q = 0; q < 8; q++) t += lsum[q];
        atomicAdd(&g_acc[1], (double)t);
    }
}

// ---------------- kernel 5: finalize --------------------------------------------
__global__ void finalize_kernel(float* out) {
    double curv = g_acc[0] / ((double)NPTS * KNN);
    double ang  = g_acc[1] / ((double)NPTS * NPAIR);
    out[0] = (float)(0.3 * curv + 0.7 * ang);
}

// ---------------- launch ---------------------------------------------------------
extern "C" void kernel_launch(void* const* d_in, const int* in_sizes, int n_in,
                              void* d_out, int out_size) {
    const float* emb      = (const float*)d_in[0];
    const float* ref_curv = (const float*)d_in[1];
    const float* ref_ang  = (const float*)d_in[2];
    float* out = (float*)d_out;

    zero_acc_kernel<<<1, 1>>>();
    norms_kernel<<<NPTS / 8, 256>>>(emb);
    gemm_sqdist_kernel<<<dim3(NPTS / 128, NPTS / 128), 256>>>(emb);
    topk_curv_kernel<<<NPTS, 256>>>(ref_curv);
    angular_kernel<<<NPTS, 256>>>(emb, ref_ang);
    finalize_kernel<<<1, 1>>>(out);
}

// round 2
// speedup vs baseline: 1.2328x; 1.2328x over previous
#include <cuda_runtime.h>
#include <cuda_bf16.h>
#include <math.h>
#include <stdint.h>

// Problem constants
#define NPTS 8192
#define DIM  512
#define KNN  15
#define NPAIR 105   // 15*14/2

// ---------------- scratch (device globals: no allocation allowed) -------------
__device__ float  g_sqdist[(size_t)NPTS * NPTS];   // 256 MB squared distances
__device__ float  g_norms[NPTS];
__device__ int    g_knni[NPTS * KNN];
__device__ double g_acc[2];                        // [0]=curv sumsq, [1]=ang sumsq

// ---------------- f32x2 packed helpers (sm_103a dual-fp32 pipe) ---------------
typedef unsigned long long u64;
__device__ __forceinline__ u64 pack2(float lo, float hi) {
    u64 r; asm("mov.b64 %0, {%1, %2};" : "=l"(r) : "f"(lo), "f"(hi)); return r;
}
__device__ __forceinline__ u64 fma2(u64 a, u64 b, u64 c) {
    u64 d; asm("fma.rn.f32x2 %0, %1, %2, %3;" : "=l"(d) : "l"(a), "l"(b), "l"(c)); return d;
}
__device__ __forceinline__ void unpack2(u64 v, float& lo, float& hi) {
    asm("mov.b64 {%0, %1}, %2;" : "=f"(lo), "=f"(hi) : "l"(v));
}

// ---------------- kernel 0: zero accumulators ---------------------------------
__global__ void zero_acc_kernel() {
    g_acc[0] = 0.0; g_acc[1] = 0.0;
}

// ---------------- kernel 1: row squared norms ----------------------------------
__global__ void norms_kernel(const float* __restrict__ E) {
    int row  = blockIdx.x * 8 + (threadIdx.x >> 5);
    int lane = threadIdx.x & 31;
    const float4* r = (const float4*)(E + (size_t)row * DIM);
    float s = 0.f;
    #pragma unroll
    for (int c4 = lane; c4 < DIM / 4; c4 += 32) {
        float4 v = r[c4];
        s = fmaf(v.x, v.x, fmaf(v.y, v.y, fmaf(v.z, v.z, fmaf(v.w, v.w, s))));
    }
    #pragma unroll
    for (int o = 16; o; o >>= 1) s += __shfl_xor_sync(0xFFFFFFFFu, s, o);
    if (!lane) g_norms[row] = s;
}

// ---------------- kernel 2: symmetric SGEMM -> squared distances ----------------
// BM=BN=128, BK=16, 256 threads, 8x8 outputs/thread, packed f32x2 FMAs.
// Triangular grid (bx<=by); register-prefetch double buffering hides LDG.
__global__ __launch_bounds__(256, 2)
void gemm_sqdist_kernel(const float* __restrict__ E) {
    // decode triangular linear index -> (bx, by), bx <= by
    int t = blockIdx.x;
    int by = (int)((sqrtf(8.0f * (float)t + 1.0f) - 1.0f) * 0.5f);
    while ((by + 1) * (by + 2) / 2 <= t) ++by;
    while (by * (by + 1) / 2 > t) --by;
    int bx = t - by * (by + 1) / 2;

    __shared__ float As[16][128];
    __shared__ float Bs[16][128];

    const int tid  = threadIdx.x;
    const int row0 = by * 128, col0 = bx * 128;

    const int la_r = tid >> 2;           // 0..63
    const int la_c = (tid & 3) * 4;      // 0,4,8,12

    const int ty = tid >> 4;             // 0..15
    const int tx = tid & 15;             // 0..15

    u64 acc[4][8];
    #pragma unroll
    for (int mp = 0; mp < 4; mp++)
        #pragma unroll
        for (int n = 0; n < 8; n++) acc[mp][n] = 0ull;

    // prologue: prefetch stage 0 into registers
    float4 pa0, pa1, pb0, pb1;
    {
        const float* baseA0 = &E[(size_t)(row0 + la_r)      * DIM + la_c];
        const float* baseA1 = &E[(size_t)(row0 + la_r + 64) * DIM + la_c];
        const float* baseB0 = &E[(size_t)(col0 + la_r)      * DIM + la_c];
        const float* baseB1 = &E[(size_t)(col0 + la_r + 64) * DIM + la_c];
        pa0 = *(const float4*)baseA0;
        pa1 = *(const float4*)baseA1;
        pb0 = *(const float4*)baseB0;
        pb1 = *(const float4*)baseB1;
    }

    for (int it = 0; it < 32; it++) {
        // store prefetched registers into smem (transposed)
        As[la_c + 0][la_r] = pa0.x; As[la_c + 1][la_r] = pa0.y;
        As[la_c + 2][la_r] = pa0.z; As[la_c + 3][la_r] = pa0.w;
        As[la_c + 0][la_r + 64] = pa1.x; As[la_c + 1][la_r + 64] = pa1.y;
        As[la_c + 2][la_r + 64] = pa1.z; As[la_c + 3][la_r + 64] = pa1.w;
        Bs[la_c + 0][la_r] = pb0.x; Bs[la_c + 1][la_r] = pb0.y;
        Bs[la_c + 2][la_r] = pb0.z; Bs[la_c + 3][la_r] = pb0.w;
        Bs[la_c + 0][la_r + 64] = pb1.x; Bs[la_c + 1][la_r + 64] = pb1.y;
        Bs[la_c + 2][la_r + 64] = pb1.z; Bs[la_c + 3][la_r + 64] = pb1.w;
        __syncthreads();

        // prefetch next stage (hidden under the 16 K-steps of FMA below)
        if (it < 31) {
            int k0 = (it + 1) * 16;
            pa0 = *(const float4*)&E[(size_t)(row0 + la_r)      * DIM + k0 + la_c];
            pa1 = *(const float4*)&E[(size_t)(row0 + la_r + 64) * DIM + k0 + la_c];
            pb0 = *(const float4*)&E[(size_t)(col0 + la_r)      * DIM + k0 + la_c];
            pb1 = *(const float4*)&E[(size_t)(col0 + la_r + 64) * DIM + k0 + la_c];
        }

        #pragma unroll
        for (int k = 0; k < 16; k++) {
            // A: 4 m-pairs, loaded directly as packed u64 (no movs)
            ulonglong2 aA = *(const ulonglong2*)&As[k][ty * 8];
            ulonglong2 aB = *(const ulonglong2*)&As[k][ty * 8 + 4];
            // B: 8 scalars, replicated into both lanes
            float4 b0 = *(const float4*)&Bs[k][tx * 8];
            float4 b1 = *(const float4*)&Bs[k][tx * 8 + 4];
            u64 bb[8];
            bb[0] = pack2(b0.x, b0.x); bb[1] = pack2(b0.y, b0.y);
            bb[2] = pack2(b0.z, b0.z); bb[3] = pack2(b0.w, b0.w);
            bb[4] = pack2(b1.x, b1.x); bb[5] = pack2(b1.y, b1.y);
            bb[6] = pack2(b1.z, b1.z); bb[7] = pack2(b1.w, b1.w);
            u64 am[4] = {aA.x, aA.y, aB.x, aB.y};
            #pragma unroll
            for (int mp = 0; mp < 4; mp++)
                #pragma unroll
                for (int n = 0; n < 8; n++)
                    acc[mp][n] = fma2(am[mp], bb[n], acc[mp][n]);
        }
        __syncthreads();
    }

    // epilogue: sq-dist, diagonal INF, vectorized stores + mirror
    const float INF = __int_as_float(0x7f800000);
    const int ibase = row0 + ty * 8;
    const int jbase = col0 + tx * 8;
    float nj[8];
    #pragma unroll
    for (int n = 0; n < 8; n++) nj[n] = g_norms[jbase + n];

    #pragma unroll
    for (int mp = 0; mp < 4; mp++) {
        float lo[8], hi[8];
        #pragma unroll
        for (int n = 0; n < 8; n++) unpack2(acc[mp][n], lo[n], hi[n]);
        #pragma unroll
        for (int half = 0; half < 2; half++) {
            int i = ibase + 2 * mp + half;
            float ni = g_norms[i];
            float out[8];
            #pragma unroll
            for (int n = 0; n < 8; n++) {
                float v = half ? hi[n] : lo[n];
                float s = fmaxf(ni + nj[n] - 2.f * v, 0.f);
                if (i == jbase + n) s = INF;
                out[n] = s;
            }
            float* dst = &g_sqdist[(size_t)i * NPTS + jbase];
            *(float4*)dst       = make_float4(out[0], out[1], out[2], out[3]);
            *(float4*)(dst + 4) = make_float4(out[4], out[5], out[6], out[7]);
            if (bx < by) {
                #pragma unroll
                for (int n = 0; n < 8; n++)
                    g_sqdist[(size_t)(jbase + n) * NPTS + i] = out[n];
            }
        }
    }
}

// ---------------- kernel 3: warp-per-row 15-NN + curvature loss -----------------
__global__ __launch_bounds__(256)
void topk_curv_kernel(const float* __restrict__ ref_curv) {
    const int row  = blockIdx.x * 8 + (threadIdx.x >> 5);
    const int lane = threadIdx.x & 31;
    const float INF = __int_as_float(0x7f800000);
    const float4* r4 = (const float4*)(g_sqdist + (size_t)row * NPTS);

    float d[16]; int ix[16];
    #pragma unroll
    for (int q = 0; q < 16; q++) { d[q] = INF; ix[q] = 0; }

#define INSERT(vv, jj)                                            \
    if ((vv) < d[15]) {                                           \
        float cv = (vv); int ci = (jj);                           \
        _Pragma("unroll")                                         \
        for (int q = 0; q < 16; q++) {                            \
            if (cv < d[q]) {                                      \
                float tf = d[q]; d[q] = cv; cv = tf;              \
                int   ti = ix[q]; ix[q] = ci; ci = ti;            \
            }                                                     \
        }                                                         \
    }

    for (int it = 0; it < NPTS / 128; it++) {
        int j4 = it * 32 + lane;
        float4 v = r4[j4];
        int jb = j4 * 4;
        float m = fminf(fminf(v.x, v.y), fminf(v.z, v.w));
        if (m < d[15]) {
            INSERT(v.x, jb);
            INSERT(v.y, jb + 1);
            INSERT(v.z, jb + 2);
            INSERT(v.w, jb + 3);
        }
    }
#undef INSERT

    // warp merge: extract global min 15 times; result s lives on lane s
    float myd = 0.f; int myi = 0;
    for (int s = 0; s < KNN; s++) {
        float m = d[0]; int src = lane;
        #pragma unroll
        for (int o = 16; o; o >>= 1) {
            float om = __shfl_xor_sync(0xFFFFFFFFu, m, o);
            int   os = __shfl_xor_sync(0xFFFFFFFFu, src, o);
            if (om < m || (om == m && os < src)) { m = om; src = os; }
        }
        int wi = __shfl_sync(0xFFFFFFFFu, ix[0], src);
        if (lane == s) { myd = m; myi = wi; }
        if (lane == src) {
            #pragma unroll
            for (int q = 0; q < 15; q++) { d[q] = d[q + 1]; ix[q] = ix[q + 1]; }
            d[15] = INF;
        }
    }

    // curvature: dd sorted ascending across lanes 0..14
    float dd = (lane < KNN) ? sqrtf(fmaxf(myd, 1e-12f)) : 0.f;
    float ssum = dd;
    #pragma unroll
    for (int o = 16; o; o >>= 1) ssum += __shfl_xor_sync(0xFFFFFFFFu, ssum, o);
    float mean = ssum / (float)KNN + 1e-8f;    // EPS_MEAN
    float df = 0.f;
    if (lane < KNN) {
        df = dd / mean - ref_curv[row * KNN + lane];
        g_knni[row * KNN + lane] = myi;
    }
    float l = df * df;
    #pragma unroll
    for (int o = 16; o; o >>= 1) l += __shfl_xor_sync(0xFFFFFFFFu, l, o);
    if (lane == 0) atomicAdd(&g_acc[0], (double)l);
}

// ---------------- kernel 4: angular signature loss ------------------------------
__global__ __launch_bounds__(256)
void angular_kernel(const float* __restrict__ E, const float* __restrict__ ref_ang) {
    const int row  = blockIdx.x;
    const int tid  = threadIdx.x;
    const int lane = tid & 31;
    const int w    = tid >> 5;

    __shared__ float ei[DIM];
    __shared__ float vh[KNN][DIM];
    __shared__ float nrm[KNN];
    __shared__ float cosv[128];
    __shared__ float lsum[8];

    // load center embedding
    if (tid < 128) {
        float4 q = *(const float4*)&E[(size_t)row * DIM + tid * 4];
        *(float4*)&ei[tid * 4] = q;
    }
    if (tid >= 105 && tid < 128) cosv[tid] = __int_as_float(0x7f800000);
    __syncthreads();

    // gather neighbors, form difference vectors, compute norms
    for (int j = w; j < KNN; j += 8) {
        int nb = g_knni[row * KNN + j];
        const float4* src = (const float4*)&E[(size_t)nb * DIM];
        float s = 0.f;
        for (int c4 = lane; c4 < DIM / 4; c4 += 32) {
            float4 q = src[c4];
            float4 e = *(const float4*)&ei[c4 * 4];
            float4 v; v.x = q.x - e.x; v.y = q.y - e.y; v.z = q.z - e.z; v.w = q.w - e.w;
            *(float4*)&vh[j][c4 * 4] = v;
            s = fmaf(v.x, v.x, fmaf(v.y, v.y, fmaf(v.z, v.z, fmaf(v.w, v.w, s))));
        }
        #pragma unroll
        for (int o = 16; o; o >>= 1) s += __shfl_xor_sync(0xFFFFFFFFu, s, o);
        if (!lane) nrm[j] = fmaxf(sqrtf(s), 1e-8f);   // EPS_NORM
    }
    __syncthreads();

    // 105 pairwise cosines
    for (int p = w; p < NPAIR; p += 8) {
        int jj = 0, rem = p;
        while (rem >= (KNN - 1) - jj) { rem -= (KNN - 1) - jj; jj++; }
        int kk = jj + 1 + rem;
        float s = 0.f;
        for (int c = lane; c < DIM; c += 32)
            s = fmaf(vh[jj][c], vh[kk][c], s);
        #pragma unroll
        for (int o = 16; o; o >>= 1) s += __shfl_xor_sync(0xFFFFFFFFu, s, o);
        if (!lane) cosv[p] = s / (nrm[jj] * nrm[kk]);
    }
    __syncthreads();

    // bitonic sort of 128 (105 real + INF padding), ascending
    for (int k = 2; k <= 128; k <<= 1) {
        for (int j2 = k >> 1; j2 > 0; j2 >>= 1) {
            if (tid < 128) {
                int ixj = tid ^ j2;
                if (ixj > tid) {
                    float a = cosv[tid], b = cosv[ixj];
                    bool up = ((tid & k) == 0);
                    if ((a > b) == up) { cosv[tid] = b; cosv[ixj] = a; }
                }
            }
            __syncthreads();
        }
    }

    float s = 0.f;
    for (int t = tid; t < NPAIR; t += 256) {
        float df = cosv[t] - ref_ang[(size_t)row * NPAIR + t];
        s = fmaf(df, df, s);
    }
    #pragma unroll
    for (int o = 16; o; o >>= 1) s += __shfl_xor_sync(0xFFFFFFFFu, s, o);
    if (!lane) lsum[w] = s;
    __syncthreads();
    if (tid == 0) {
        float t = 0.f;
        #pragma unroll
        for (int q = 0; q < 8; q++) t += lsum[q];
        atomicAdd(&g_acc[1], (double)t);
    }
}

// ---------------- kernel 5: finalize --------------------------------------------
__global__ void finalize_kernel(float* out) {
    double curv = g_acc[0] / ((double)NPTS * KNN);
    double ang  = g_acc[1] / ((double)NPTS * NPAIR);
    out[0] = (float)(0.3 * curv + 0.7 * ang);
}

// ---------------- launch ---------------------------------------------------------
extern "C" void kernel_launch(void* const* d_in, const int* in_sizes, int n_in,
                              void* d_out, int out_size) {
    const float* emb      = (const float*)d_in[0];
    const float* ref_curv = (const float*)d_in[1];
    const float* ref_ang  = (const float*)d_in[2];
    float* out = (float*)d_out;

    const int NB = 64;                      // NPTS / 128
    const int TRI = NB * (NB + 1) / 2;      // 2080 triangular tiles

    zero_acc_kernel<<<1, 1>>>();
    norms_kernel<<<NPTS / 8, 256>>>(emb);
    gemm_sqdist_kernel<<<TRI, 256>>>(emb);
    topk_curv_kernel<<<NPTS / 8, 256>>>(ref_curv);
    angular_kernel<<<NPTS, 256>>>(emb, ref_ang);
    finalize_kernel<<<1, 1>>>(out);
}

// round 3
// speedup vs baseline: 1.7684x; 1.4345x over previous
#include <cuda_runtime.h>
#include <cuda_bf16.h>
#include <math.h>
#include <stdint.h>

// Problem constants
#define NPTS 8192
#define DIM  512
#define KNN  15
#define NPAIR 105   // 15*14/2
#define FULLM 0xFFFFFFFFu

// ---------------- scratch (device globals: no allocation allowed) -------------
__device__ float  g_sqdist[(size_t)NPTS * NPTS];   // 256 MB squared distances
__device__ float  g_norms[NPTS];
__device__ int    g_knni[NPTS * KNN];
__device__ double g_acc[2];                        // [0]=curv sumsq, [1]=ang sumsq

// ---------------- f32x2 packed helpers (sm_103a dual-fp32 pipe) ---------------
typedef unsigned long long u64;
__device__ __forceinline__ u64 pack2(float lo, float hi) {
    u64 r; asm("mov.b64 %0, {%1, %2};" : "=l"(r) : "f"(lo), "f"(hi)); return r;
}
__device__ __forceinline__ u64 fma2(u64 a, u64 b, u64 c) {
    u64 d; asm("fma.rn.f32x2 %0, %1, %2, %3;" : "=l"(d) : "l"(a), "l"(b), "l"(c)); return d;
}
__device__ __forceinline__ void unpack2(u64 v, float& lo, float& hi) {
    asm("mov.b64 {%0, %1}, %2;" : "=f"(lo), "=f"(hi) : "l"(v));
}

// ---------------- kernel 0: zero accumulators ---------------------------------
__global__ void zero_acc_kernel() {
    g_acc[0] = 0.0; g_acc[1] = 0.0;
}

// ---------------- kernel 1: row squared norms ----------------------------------
__global__ void norms_kernel(const float* __restrict__ E) {
    int row  = blockIdx.x * 8 + (threadIdx.x >> 5);
    int lane = threadIdx.x & 31;
    const float4* r = (const float4*)(E + (size_t)row * DIM);
    float s = 0.f;
    #pragma unroll
    for (int c4 = lane; c4 < DIM / 4; c4 += 32) {
        float4 v = r[c4];
        s = fmaf(v.x, v.x, fmaf(v.y, v.y, fmaf(v.z, v.z, fmaf(v.w, v.w, s))));
    }
    #pragma unroll
    for (int o = 16; o; o >>= 1) s += __shfl_xor_sync(FULLM, s, o);
    if (!lane) g_norms[row] = s;
}

// ---------------- kernel 2: symmetric SGEMM -> squared distances ----------------
// BM=BN=128, BK=16, 256 threads, 8x8 outputs/thread, packed f32x2 FMAs.
// Double-buffered smem (1 barrier/stage), padded stride 132 (reduced bank
// conflicts), smem-transposed coalesced mirror stores.
__global__ __launch_bounds__(256, 2)
void gemm_sqdist_kernel(const float* __restrict__ E) {
    // decode triangular linear index -> (bx, by), bx <= by
    int t = blockIdx.x;
    int by = (int)((sqrtf(8.0f * (float)t + 1.0f) - 1.0f) * 0.5f);
    while ((by + 1) * (by + 2) / 2 <= t) ++by;
    while (by * (by + 1) / 2 > t) --by;
    int bx = t - by * (by + 1) / 2;

    __shared__ float As[2][16][132];
    __shared__ float Bs[2][16][132];

    const int tid  = threadIdx.x;
    const int row0 = by * 128, col0 = bx * 128;

    const int la_r = tid >> 2;           // 0..63
    const int la_c = (tid & 3) * 4;      // 0,4,8,12

    const int ty = tid >> 4;             // 0..15
    const int tx = tid & 15;             // 0..15

    u64 acc[4][8];
    #pragma unroll
    for (int mp = 0; mp < 4; mp++)
        #pragma unroll
        for (int n = 0; n < 8; n++) acc[mp][n] = 0ull;

    const float* baseA0 = &E[(size_t)(row0 + la_r)      * DIM + la_c];
    const float* baseA1 = &E[(size_t)(row0 + la_r + 64) * DIM + la_c];
    const float* baseB0 = &E[(size_t)(col0 + la_r)      * DIM + la_c];
    const float* baseB1 = &E[(size_t)(col0 + la_r + 64) * DIM + la_c];

    // prologue: prefetch stage 0 and store into buffer 0
    float4 pa0 = *(const float4*)baseA0;
    float4 pa1 = *(const float4*)baseA1;
    float4 pb0 = *(const float4*)baseB0;
    float4 pb1 = *(const float4*)baseB1;
    {
        float (*A)[132] = As[0];
        float (*B)[132] = Bs[0];
        A[la_c + 0][la_r] = pa0.x; A[la_c + 1][la_r] = pa0.y;
        A[la_c + 2][la_r] = pa0.z; A[la_c + 3][la_r] = pa0.w;
        A[la_c + 0][la_r + 64] = pa1.x; A[la_c + 1][la_r + 64] = pa1.y;
        A[la_c + 2][la_r + 64] = pa1.z; A[la_c + 3][la_r + 64] = pa1.w;
        B[la_c + 0][la_r] = pb0.x; B[la_c + 1][la_r] = pb0.y;
        B[la_c + 2][la_r] = pb0.z; B[la_c + 3][la_r] = pb0.w;
        B[la_c + 0][la_r + 64] = pb1.x; B[la_c + 1][la_r + 64] = pb1.y;
        B[la_c + 2][la_r + 64] = pb1.z; B[la_c + 3][la_r + 64] = pb1.w;
    }
    __syncthreads();

    for (int it = 0; it < 32; it++) {
        const int cur = it & 1;
        // prefetch next stage into registers (hidden under 16 K-steps of FMA)
        if (it < 31) {
            int k0 = (it + 1) * 16;
            pa0 = *(const float4*)(baseA0 + k0);
            pa1 = *(const float4*)(baseA1 + k0);
            pb0 = *(const float4*)(baseB0 + k0);
            pb1 = *(const float4*)(baseB1 + k0);
        }

        float (*Ac)[132] = As[cur];
        float (*Bc)[132] = Bs[cur];
        #pragma unroll
        for (int k = 0; k < 16; k++) {
            ulonglong2 aA = *(const ulonglong2*)&Ac[k][ty * 8];
            ulonglong2 aB = *(const ulonglong2*)&Ac[k][ty * 8 + 4];
            float4 b0 = *(const float4*)&Bc[k][tx * 8];
            float4 b1 = *(const float4*)&Bc[k][tx * 8 + 4];
            u64 bb[8];
            bb[0] = pack2(b0.x, b0.x); bb[1] = pack2(b0.y, b0.y);
            bb[2] = pack2(b0.z, b0.z); bb[3] = pack2(b0.w, b0.w);
            bb[4] = pack2(b1.x, b1.x); bb[5] = pack2(b1.y, b1.y);
            bb[6] = pack2(b1.z, b1.z); bb[7] = pack2(b1.w, b1.w);
            u64 am[4] = {aA.x, aA.y, aB.x, aB.y};
            #pragma unroll
            for (int mp = 0; mp < 4; mp++)
                #pragma unroll
                for (int n = 0; n < 8; n++)
                    acc[mp][n] = fma2(am[mp], bb[n], acc[mp][n]);
        }

        // store prefetched registers into the OTHER buffer, then 1 barrier
        if (it < 31) {
            float (*A)[132] = As[cur ^ 1];
            float (*B)[132] = Bs[cur ^ 1];
            A[la_c + 0][la_r] = pa0.x; A[la_c + 1][la_r] = pa0.y;
            A[la_c + 2][la_r] = pa0.z; A[la_c + 3][la_r] = pa0.w;
            A[la_c + 0][la_r + 64] = pa1.x; A[la_c + 1][la_r + 64] = pa1.y;
            A[la_c + 2][la_r + 64] = pa1.z; A[la_c + 3][la_r + 64] = pa1.w;
            B[la_c + 0][la_r] = pb0.x; B[la_c + 1][la_r] = pb0.y;
            B[la_c + 2][la_r] = pb0.z; B[la_c + 3][la_r] = pb0.w;
            B[la_c + 0][la_r + 64] = pb1.x; B[la_c + 1][la_r + 64] = pb1.y;
            B[la_c + 2][la_r + 64] = pb1.z; B[la_c + 3][la_r + 64] = pb1.w;
            __syncthreads();
        }
    }

    // ---------------- epilogue ----------------
    const float INF = __int_as_float(0x7f800000);
    const int ibase = row0 + ty * 8;
    const int jbase = col0 + tx * 8;
    float nj[8];
    #pragma unroll
    for (int n = 0; n < 8; n++) nj[n] = g_norms[jbase + n];

    float out[8][8];   // [local row r][n]
    #pragma unroll
    for (int mp = 0; mp < 4; mp++) {
        #pragma unroll
        for (int n = 0; n < 8; n++) {
            float lo, hi;
            unpack2(acc[mp][n], lo, hi);
            out[2 * mp][n]     = lo;
            out[2 * mp + 1][n] = hi;
        }
    }
    #pragma unroll
    for (int r = 0; r < 8; r++) {
        int i = ibase + r;
        float ni = g_norms[i];
        #pragma unroll
        for (int n = 0; n < 8; n++) {
            float s = fmaxf(ni + nj[n] - 2.f * out[r][n], 0.f);
            if (i == jbase + n) s = INF;
            out[r][n] = s;
        }
        float* dst = &g_sqdist[(size_t)i * NPTS + jbase];
        *(float4*)dst       = make_float4(out[r][0], out[r][1], out[r][2], out[r][3]);
        *(float4*)(dst + 4) = make_float4(out[r][4], out[r][5], out[r][6], out[r][7]);
    }

    // mirror: transpose 16 j-rows at a time through smem, coalesced STG.128
    if (bx < by) {
        float (*S)[132] = As[0];
        #pragma unroll 1
        for (int c = 0; c < 8; c++) {
            __syncthreads();
            if ((tx >> 1) == c) {
                int jsub = (tx & 1) * 8;
                #pragma unroll
                for (int n = 0; n < 8; n++) {
                    *(float4*)&S[jsub + n][ty * 8] =
                        make_float4(out[0][n], out[1][n], out[2][n], out[3][n]);
                    *(float4*)&S[jsub + n][ty * 8 + 4] =
                        make_float4(out[4][n], out[5][n], out[6][n], out[7][n]);
                }
            }
            __syncthreads();
            int jl = tid >> 4;   // 0..15
            int s4 = tid & 15;   // 0..15
            float4* dst = (float4*)&g_sqdist[(size_t)(col0 + c * 16 + jl) * NPTS + row0];
            dst[s4]      = *(float4*)&S[jl][s4 * 4];
            dst[s4 + 16] = *(float4*)&S[jl][(s4 + 16) * 4];
        }
    }
}

// ---------------- kernel 3: warp-per-row 15-NN, warp-distributed sorted list ----
__global__ __launch_bounds__(256)
void topk_curv_kernel(const float* __restrict__ ref_curv) {
    const int row  = blockIdx.x * 8 + (threadIdx.x >> 5);
    const int lane = threadIdx.x & 31;
    const float INF = __int_as_float(0x7f800000);
    const float4* r4 = (const float4*)(g_sqdist + (size_t)row * NPTS);

    // lanes 0..14 hold the current 15 smallest, sorted ascending.
    float lv = INF; int li = 0;
    float T  = INF;               // 15th smallest so far (lane 14), broadcast

    #pragma unroll 1
    for (int it = 0; it < NPTS / 128; it++) {
        float4 v = r4[it * 32 + lane];
        float m = fminf(fminf(v.x, v.y), fminf(v.z, v.w));
        unsigned ball = __ballot_sync(FULLM, m < T);
        while (ball) {
            int src = __ffs(ball) - 1;
            ball &= ball - 1;
            float w0 = __shfl_sync(FULLM, v.x, src);
            float w1 = __shfl_sync(FULLM, v.y, src);
            float w2 = __shfl_sync(FULLM, v.z, src);
            float w3 = __shfl_sync(FULLM, v.w, src);
            int jb = (it * 32 + src) * 4;
            float wv[4] = {w0, w1, w2, w3};
            #pragma unroll
            for (int c = 0; c < 4; c++) {
                float val = wv[c];
                if (val < T) {                 // warp-uniform
                    unsigned less = __ballot_sync(FULLM, lv < val);
                    int pos = __popc(less);    // insertion slot (<= 14)
                    float pv = __shfl_up_sync(FULLM, lv, 1);
                    int   pi = __shfl_up_sync(FULLM, li, 1);
                    if (lane == pos)                      { lv = val; li = jb + c; }
                    else if (lane > pos && lane < KNN)    { lv = pv;  li = pi;     }
                    T = __shfl_sync(FULLM, lv, KNN - 1);
                }
            }
        }
    }

    // curvature: lv on lanes 0..14 = sorted kNN sq-distances
    float dd = (lane < KNN) ? sqrtf(fmaxf(lv, 1e-12f)) : 0.f;
    float ssum = dd;
    #pragma unroll
    for (int o = 16; o; o >>= 1) ssum += __shfl_xor_sync(FULLM, ssum, o);
    float mean = ssum / (float)KNN + 1e-8f;    // EPS_MEAN
    float df = 0.f;
    if (lane < KNN) {
        df = dd / mean - ref_curv[row * KNN + lane];
        g_knni[row * KNN + lane] = li;
    }
    float l = df * df;
    #pragma unroll
    for (int o = 16; o; o >>= 1) l += __shfl_xor_sync(FULLM, l, o);
    if (lane == 0) atomicAdd(&g_acc[0], (double)l);
}

// ---------------- kernel 4: angular signature loss ------------------------------
__global__ __launch_bounds__(256)
void angular_kernel(const float* __restrict__ E, const float* __restrict__ ref_ang) {
    const int row  = blockIdx.x;
    const int tid  = threadIdx.x;
    const int lane = tid & 31;
    const int w    = tid >> 5;

    __shared__ float ei[DIM];
    __shared__ float vh[KNN][DIM];
    __shared__ float nrm[KNN];
    __shared__ float cosv[128];
    __shared__ float lsum[8];

    if (tid < 128) {
        float4 q = *(const float4*)&E[(size_t)row * DIM + tid * 4];
        *(float4*)&ei[tid * 4] = q;
    }
    if (tid >= 105 && tid < 128) cosv[tid] = __int_as_float(0x7f800000);
    __syncthreads();

    for (int j = w; j < KNN; j += 8) {
        int nb = g_knni[row * KNN + j];
        const float4* src = (const float4*)&E[(size_t)nb * DIM];
        float s = 0.f;
        for (int c4 = lane; c4 < DIM / 4; c4 += 32) {
            float4 q = src[c4];
            float4 e = *(const float4*)&ei[c4 * 4];
            float4 v; v.x = q.x - e.x; v.y = q.y - e.y; v.z = q.z - e.z; v.w = q.w - e.w;
            *(float4*)&vh[j][c4 * 4] = v;
            s = fmaf(v.x, v.x, fmaf(v.y, v.y, fmaf(v.z, v.z, fmaf(v.w, v.w, s))));
        }
        #pragma unroll
        for (int o = 16; o; o >>= 1) s += __shfl_xor_sync(FULLM, s, o);
        if (!lane) nrm[j] = fmaxf(sqrtf(s), 1e-8f);   // EPS_NORM
    }
    __syncthreads();

    for (int p = w; p < NPAIR; p += 8) {
        int jj = 0, rem = p;
        while (rem >= (KNN - 1) - jj) { rem -= (KNN - 1) - jj; jj++; }
        int kk = jj + 1 + rem;
        float s = 0.f;
        for (int c = lane; c < DIM; c += 32)
            s = fmaf(vh[jj][c], vh[kk][c], s);
        #pragma unroll
        for (int o = 16; o; o >>= 1) s += __shfl_xor_sync(FULLM, s, o);
        if (!lane) cosv[p] = s / (nrm[jj] * nrm[kk]);
    }
    __syncthreads();

    for (int k = 2; k <= 128; k <<= 1) {
        for (int j2 = k >> 1; j2 > 0; j2 >>= 1) {
            if (tid < 128) {
                int ixj = tid ^ j2;
                if (ixj > tid) {
                    float a = cosv[tid], b = cosv[ixj];
                    bool up = ((tid & k) == 0);
                    if ((a > b) == up) { cosv[tid] = b; cosv[ixj] = a; }
                }
            }
            __syncthreads();
        }
    }

    float s = 0.f;
    for (int t2 = tid; t2 < NPAIR; t2 += 256) {
        float df = cosv[t2] - ref_ang[(size_t)row * NPAIR + t2];
        s = fmaf(df, df, s);
    }
    #pragma unroll
    for (int o = 16; o; o >>= 1) s += __shfl_xor_sync(FULLM, s, o);
    if (!lane) lsum[w] = s;
    __syncthreads();
    if (tid == 0) {
        float t2 = 0.f;
        #pragma unroll
        for (int q = 0; q < 8; q++) t2 += lsum[q];
        atomicAdd(&g_acc[1], (double)t2);
    }
}

// ---------------- kernel 5: finalize --------------------------------------------
__global__ void finalize_kernel(float* out) {
    double curv = g_acc[0] / ((double)NPTS * KNN);
    double ang  = g_acc[1] / ((double)NPTS * NPAIR);
    out[0] = (float)(0.3 * curv + 0.7 * ang);
}

// ---------------- launch ---------------------------------------------------------
extern "C" void kernel_launch(void* const* d_in, const int* in_sizes, int n_in,
                              void* d_out, int out_size) {
    const float* emb      = (const float*)d_in[0];
    const float* ref_curv = (const float*)d_in[1];
    const float* ref_ang  = (const float*)d_in[2];
    float* out = (float*)d_out;

    const int NB = 64;                      // NPTS / 128
    const int TRI = NB * (NB + 1) / 2;      // 2080 triangular tiles

    zero_acc_kernel<<<1, 1>>>();
    norms_kernel<<<NPTS / 8, 256>>>(emb);
    gemm_sqdist_kernel<<<TRI, 256>>>(emb);
    topk_curv_kernel<<<NPTS / 8, 256>>>(ref_curv);
    angular_kernel<<<NPTS, 256>>>(emb, ref_ang);
    finalize_kernel<<<1, 1>>>(out);
}

// round 4
// speedup vs baseline: 1.9212x; 1.0864x over previous
#include <cuda_runtime.h>
#include <cuda_bf16.h>
#include <math.h>
#include <stdint.h>

// Problem constants
#define NPTS 8192
#define DIM  512
#define KNN  15
#define NPAIR 105   // 15*14/2
#define FULLM 0xFFFFFFFFu

// ---------------- scratch (device globals: no allocation allowed) -------------
__device__ float  g_sqdist[(size_t)NPTS * NPTS];   // 256 MB squared distances
__device__ float  g_norms[NPTS];
__device__ int    g_knni[NPTS * KNN];
__device__ double g_acc[2];                        // [0]=curv sumsq, [1]=ang sumsq

// ---------------- f32x2 packed helpers (sm_103a dual-fp32 pipe) ---------------
typedef unsigned long long u64;
__device__ __forceinline__ u64 pack2(float lo, float hi) {
    u64 r; asm("mov.b64 %0, {%1, %2};" : "=l"(r) : "f"(lo), "f"(hi)); return r;
}
__device__ __forceinline__ u64 fma2(u64 a, u64 b, u64 c) {
    u64 d; asm("fma.rn.f32x2 %0, %1, %2, %3;" : "=l"(d) : "l"(a), "l"(b), "l"(c)); return d;
}
__device__ __forceinline__ void unpack2(u64 v, float& lo, float& hi) {
    asm("mov.b64 {%0, %1}, %2;" : "=f"(lo), "=f"(hi) : "l"(v));
}

// ---------------- kernel 0: zero accumulators ---------------------------------
__global__ void zero_acc_kernel() {
    g_acc[0] = 0.0; g_acc[1] = 0.0;
}

// ---------------- kernel 1: row squared norms ----------------------------------
__global__ void norms_kernel(const float* __restrict__ E) {
    int row  = blockIdx.x * 8 + (threadIdx.x >> 5);
    int lane = threadIdx.x & 31;
    const float4* r = (const float4*)(E + (size_t)row * DIM);
    float s = 0.f;
    #pragma unroll
    for (int c4 = lane; c4 < DIM / 4; c4 += 32) {
        float4 v = r[c4];
        s = fmaf(v.x, v.x, fmaf(v.y, v.y, fmaf(v.z, v.z, fmaf(v.w, v.w, s))));
    }
    #pragma unroll
    for (int o = 16; o; o >>= 1) s += __shfl_xor_sync(FULLM, s, o);
    if (!lane) g_norms[row] = s;
}

// ---------------- kernel 2: symmetric SGEMM -> squared distances ----------------
// BM=BN=128, BK=16, 256 threads. Split 4+4 thread tile: rows {ty*4+r, 64+ty*4+r},
// cols {tx*4+j, 64+tx*4+j}. B LDS conflict-free (consecutive 16B), B feeds fma2
// directly as packed column pairs. Double-buffered smem, 1 barrier/stage.
__global__ __launch_bounds__(256, 2)
void gemm_sqdist_kernel(const float* __restrict__ E) {
    // decode triangular linear index -> (bx, by), bx <= by
    int t = blockIdx.x;
    int by = (int)((sqrtf(8.0f * (float)t + 1.0f) - 1.0f) * 0.5f);
    while ((by + 1) * (by + 2) / 2 <= t) ++by;
    while (by * (by + 1) / 2 > t) --by;
    int bx = t - by * (by + 1) / 2;

    __shared__ float As[2][16][132];
    __shared__ float Bs[2][16][132];

    const int tid  = threadIdx.x;
    const int row0 = by * 128, col0 = bx * 128;

    const int la_r = tid >> 2;           // 0..63
    const int la_c = (tid & 3) * 4;      // 0,4,8,12

    const int ty = tid >> 4;             // 0..15
    const int tx = tid & 15;             // 0..15

    u64 acc[8][4];                        // [row r][col pair p]
    #pragma unroll
    for (int r = 0; r < 8; r++)
        #pragma unroll
        for (int p = 0; p < 4; p++) acc[r][p] = 0ull;

    const float* baseA0 = &E[(size_t)(row0 + la_r)      * DIM + la_c];
    const float* baseA1 = &E[(size_t)(row0 + la_r + 64) * DIM + la_c];
    const float* baseB0 = &E[(size_t)(col0 + la_r)      * DIM + la_c];
    const float* baseB1 = &E[(size_t)(col0 + la_r + 64) * DIM + la_c];

    // prologue: prefetch stage 0 and store into buffer 0
    float4 pa0 = *(const float4*)baseA0;
    float4 pa1 = *(const float4*)baseA1;
    float4 pb0 = *(const float4*)baseB0;
    float4 pb1 = *(const float4*)baseB1;
    {
        float (*A)[132] = As[0];
        float (*B)[132] = Bs[0];
        A[la_c + 0][la_r] = pa0.x; A[la_c + 1][la_r] = pa0.y;
        A[la_c + 2][la_r] = pa0.z; A[la_c + 3][la_r] = pa0.w;
        A[la_c + 0][la_r + 64] = pa1.x; A[la_c + 1][la_r + 64] = pa1.y;
        A[la_c + 2][la_r + 64] = pa1.z; A[la_c + 3][la_r + 64] = pa1.w;
        B[la_c + 0][la_r] = pb0.x; B[la_c + 1][la_r] = pb0.y;
        B[la_c + 2][la_r] = pb0.z; B[la_c + 3][la_r] = pb0.w;
        B[la_c + 0][la_r + 64] = pb1.x; B[la_c + 1][la_r + 64] = pb1.y;
        B[la_c + 2][la_r + 64] = pb1.z; B[la_c + 3][la_r + 64] = pb1.w;
    }
    __syncthreads();

    for (int it = 0; it < 32; it++) {
        const int cur = it & 1;
        if (it < 31) {
            int k0 = (it + 1) * 16;
            pa0 = *(const float4*)(baseA0 + k0);
            pa1 = *(const float4*)(baseA1 + k0);
            pb0 = *(const float4*)(baseB0 + k0);
            pb1 = *(const float4*)(baseB1 + k0);
        }

        float (*Ac)[132] = As[cur];
        float (*Bc)[132] = Bs[cur];
        #pragma unroll
        for (int k = 0; k < 16; k++) {
            float4 a0 = *(const float4*)&Ac[k][ty * 4];         // rows ty*4+0..3
            float4 a1 = *(const float4*)&Ac[k][ty * 4 + 64];    // rows 64+ty*4+0..3
            ulonglong2 bv0 = *(const ulonglong2*)&Bc[k][tx * 4];      // cols tx*4+0..3
            ulonglong2 bv1 = *(const ulonglong2*)&Bc[k][tx * 4 + 64]; // cols 64+tx*4+0..3
            u64 bcp[4] = {bv0.x, bv0.y, bv1.x, bv1.y};
            float ra[8] = {a0.x, a0.y, a0.z, a0.w, a1.x, a1.y, a1.z, a1.w};
            #pragma unroll
            for (int r = 0; r < 8; r++) {
                u64 am = pack2(ra[r], ra[r]);
                #pragma unroll
                for (int p = 0; p < 4; p++)
                    acc[r][p] = fma2(am, bcp[p], acc[r][p]);
            }
        }

        if (it < 31) {
            float (*A)[132] = As[cur ^ 1];
            float (*B)[132] = Bs[cur ^ 1];
            A[la_c + 0][la_r] = pa0.x; A[la_c + 1][la_r] = pa0.y;
            A[la_c + 2][la_r] = pa0.z; A[la_c + 3][la_r] = pa0.w;
            A[la_c + 0][la_r + 64] = pa1.x; A[la_c + 1][la_r + 64] = pa1.y;
            A[la_c + 2][la_r + 64] = pa1.z; A[la_c + 3][la_r + 64] = pa1.w;
            B[la_c + 0][la_r] = pb0.x; B[la_c + 1][la_r] = pb0.y;
            B[la_c + 2][la_r] = pb0.z; B[la_c + 3][la_r] = pb0.w;
            B[la_c + 0][la_r + 64] = pb1.x; B[la_c + 1][la_r + 64] = pb1.y;
            B[la_c + 2][la_r + 64] = pb1.z; B[la_c + 3][la_r + 64] = pb1.w;
            __syncthreads();
        }
    }

    // ---------------- epilogue ----------------
    const float INF = __int_as_float(0x7f800000);
    // out[r][n]: rows RI[r] = row0 + (r<4 ? ty*4+r : 64+ty*4+r-4)
    //            cols CJ[n] = col0 + (n<4 ? tx*4+n : 64+tx*4+n-4)
    const int jb0 = col0 + tx * 4;
    const int jb1 = col0 + 64 + tx * 4;
    float nj[8];
    #pragma unroll
    for (int n = 0; n < 4; n++) { nj[n] = g_norms[jb0 + n]; nj[n + 4] = g_norms[jb1 + n]; }

    float out[8][8];
    #pragma unroll
    for (int r = 0; r < 8; r++) {
        #pragma unroll
        for (int p = 0; p < 4; p++) {
            float lo, hi;
            unpack2(acc[r][p], lo, hi);
            out[r][p * 2]     = lo;
            out[r][p * 2 + 1] = hi;
        }
    }
    #pragma unroll
    for (int r = 0; r < 8; r++) {
        int i = row0 + (r < 4 ? ty * 4 + r : 64 + ty * 4 + (r - 4));
        float ni = g_norms[i];
        #pragma unroll
        for (int n = 0; n < 8; n++) {
            int j = (n < 4) ? jb0 + n : jb1 + (n - 4);
            float s = fmaxf(ni + nj[n] - 2.f * out[r][n], 0.f);
            if (i == j) s = INF;
            out[r][n] = s;
        }
        float* dst = &g_sqdist[(size_t)i * NPTS];
        *(float4*)(dst + jb0) = make_float4(out[r][0], out[r][1], out[r][2], out[r][3]);
        *(float4*)(dst + jb1) = make_float4(out[r][4], out[r][5], out[r][6], out[r][7]);
    }

    // mirror: stage 16 j-rows at a time through smem, coalesced STG.128
    if (bx < by) {
        float (*S)[132] = As[0];
        #pragma unroll 1
        for (int g = 0; g < 8; g++) {
            const int half = g >> 2;      // 0: cols tx*4.., 1: cols 64+tx*4..
            const int gi   = g & 3;       // tx quartet
            __syncthreads();
            if ((tx >> 2) == gi) {
                #pragma unroll
                for (int j = 0; j < 4; j++) {
                    int n  = half * 4 + j;
                    int cl = (tx & 3) * 4 + j;       // local col within group
                    *(float4*)&S[cl][ty * 4] =
                        make_float4(out[0][n], out[1][n], out[2][n], out[3][n]);
                    *(float4*)&S[cl][ty * 4 + 64] =
                        make_float4(out[4][n], out[5][n], out[6][n], out[7][n]);
                }
            }
            __syncthreads();
            int jl = tid >> 4;   // 0..15
            int s4 = tid & 15;   // 0..15
            int jrow = col0 + half * 64 + gi * 16 + jl;
            float4* dst = (float4*)&g_sqdist[(size_t)jrow * NPTS + row0];
            dst[s4]      = *(float4*)&S[jl][s4 * 4];
            dst[s4 + 16] = *(float4*)&S[jl][(s4 + 16) * 4];
        }
    }
}

// ---------------- kernel 3: warp-per-row 15-NN, warp-distributed sorted list ----
__global__ __launch_bounds__(256)
void topk_curv_kernel(const float* __restrict__ ref_curv) {
    const int row  = blockIdx.x * 8 + (threadIdx.x >> 5);
    const int lane = threadIdx.x & 31;
    const float INF = __int_as_float(0x7f800000);
    const float4* r4 = (const float4*)(g_sqdist + (size_t)row * NPTS);

    // lanes 0..14 hold the current 15 smallest, sorted ascending.
    float lv = INF; int li = 0;
    float T  = INF;               // 15th smallest so far (lane 14), broadcast

    #pragma unroll 1
    for (int it = 0; it < NPTS / 128; it++) {
        float4 v = r4[it * 32 + lane];
        float m = fminf(fminf(v.x, v.y), fminf(v.z, v.w));
        unsigned ball = __ballot_sync(FULLM, m < T);
        while (ball) {
            int src = __ffs(ball) - 1;
            ball &= ball - 1;
            float w0 = __shfl_sync(FULLM, v.x, src);
            float w1 = __shfl_sync(FULLM, v.y, src);
            float w2 = __shfl_sync(FULLM, v.z, src);
            float w3 = __shfl_sync(FULLM, v.w, src);
            int jb = (it * 32 + src) * 4;
            float wv[4] = {w0, w1, w2, w3};
            #pragma unroll
            for (int c = 0; c < 4; c++) {
                float val = wv[c];
                if (val < T) {                 // warp-uniform
                    unsigned less = __ballot_sync(FULLM, lv < val);
                    int pos = __popc(less);    // insertion slot (<= 14)
                    float pv = __shfl_up_sync(FULLM, lv, 1);
                    int   pi = __shfl_up_sync(FULLM, li, 1);
                    if (lane == pos)                      { lv = val; li = jb + c; }
                    else if (lane > pos && lane < KNN)    { lv = pv;  li = pi;     }
                    T = __shfl_sync(FULLM, lv, KNN - 1);
                }
            }
        }
    }

    // curvature: lv on lanes 0..14 = sorted kNN sq-distances
    float dd = (lane < KNN) ? sqrtf(fmaxf(lv, 1e-12f)) : 0.f;
    float ssum = dd;
    #pragma unroll
    for (int o = 16; o; o >>= 1) ssum += __shfl_xor_sync(FULLM, ssum, o);
    float mean = ssum / (float)KNN + 1e-8f;    // EPS_MEAN
    float df = 0.f;
    if (lane < KNN) {
        df = dd / mean - ref_curv[row * KNN + lane];
        g_knni[row * KNN + lane] = li;
    }
    float l = df * df;
    #pragma unroll
    for (int o = 16; o; o >>= 1) l += __shfl_xor_sync(FULLM, l, o);
    if (lane == 0) atomicAdd(&g_acc[0], (double)l);
}

// ---------------- kernel 4: angular signature loss ------------------------------
__global__ __launch_bounds__(256)
void angular_kernel(const float* __restrict__ E, const float* __restrict__ ref_ang) {
    const int row  = blockIdx.x;
    const int tid  = threadIdx.x;
    const int lane = tid & 31;
    const int w    = tid >> 5;

    __shared__ float ei[DIM];
    __shared__ float vh[KNN][DIM];
    __shared__ float nrm[KNN];
    __shared__ float cosv[128];
    __shared__ float lsum[8];

    if (tid < 128) {
        float4 q = *(const float4*)&E[(size_t)row * DIM + tid * 4];
        *(float4*)&ei[tid * 4] = q;
    }
    if (tid >= 105 && tid < 128) cosv[tid] = __int_as_float(0x7f800000);
    __syncthreads();

    for (int j = w; j < KNN; j += 8) {
        int nb = g_knni[row * KNN + j];
        const float4* src = (const float4*)&E[(size_t)nb * DIM];
        float s = 0.f;
        for (int c4 = lane; c4 < DIM / 4; c4 += 32) {
            float4 q = src[c4];
            float4 e = *(const float4*)&ei[c4 * 4];
            float4 v; v.x = q.x - e.x; v.y = q.y - e.y; v.z = q.z - e.z; v.w = q.w - e.w;
            *(float4*)&vh[j][c4 * 4] = v;
            s = fmaf(v.x, v.x, fmaf(v.y, v.y, fmaf(v.z, v.z, fmaf(v.w, v.w, s))));
        }
        #pragma unroll
        for (int o = 16; o; o >>= 1) s += __shfl_xor_sync(FULLM, s, o);
        if (!lane) nrm[j] = fmaxf(sqrtf(s), 1e-8f);   // EPS_NORM
    }
    __syncthreads();

    for (int p = w; p < NPAIR; p += 8) {
        int jj = 0, rem = p;
        while (rem >= (KNN - 1) - jj) { rem -= (KNN - 1) - jj; jj++; }
        int kk = jj + 1 + rem;
        float s = 0.f;
        for (int c = lane; c < DIM; c += 32)
            s = fmaf(vh[jj][c], vh[kk][c], s);
        #pragma unroll
        for (int o = 16; o; o >>= 1) s += __shfl_xor_sync(FULLM, s, o);
        if (!lane) cosv[p] = s / (nrm[jj] * nrm[kk]);
    }
    __syncthreads();

    for (int k = 2; k <= 128; k <<= 1) {
        for (int j2 = k >> 1; j2 > 0; j2 >>= 1) {
            if (tid < 128) {
                int ixj = tid ^ j2;
                if (ixj > tid) {
                    float a = cosv[tid], b = cosv[ixj];
                    bool up = ((tid & k) == 0);
                    if ((a > b) == up) { cosv[tid] = b; cosv[ixj] = a; }
                }
            }
            __syncthreads();
        }
    }

    float s = 0.f;
    for (int t2 = tid; t2 < NPAIR; t2 += 256) {
        float df = cosv[t2] - ref_ang[(size_t)row * NPAIR + t2];
        s = fmaf(df, df, s);
    }
    #pragma unroll
    for (int o = 16; o; o >>= 1) s += __shfl_xor_sync(FULLM, s, o);
    if (!lane) lsum[w] = s;
    __syncthreads();
    if (tid == 0) {
        float t2 = 0.f;
        #pragma unroll
        for (int q = 0; q < 8; q++) t2 += lsum[q];
        atomicAdd(&g_acc[1], (double)t2);
    }
}

// ---------------- kernel 5: finalize --------------------------------------------
__global__ void finalize_kernel(float* out) {
    double curv = g_acc[0] / ((double)NPTS * KNN);
    double ang  = g_acc[1] / ((double)NPTS * NPAIR);
    out[0] = (float)(0.3 * curv + 0.7 * ang);
}

// ---------------- launch ---------------------------------------------------------
extern "C" void kernel_launch(void* const* d_in, const int* in_sizes, int n_in,
                              void* d_out, int out_size) {
    const float* emb      = (const float*)d_in[0];
    const float* ref_curv = (const float*)d_in[1];
    const float* ref_ang  = (const float*)d_in[2];
    float* out = (float*)d_out;

    const int NB = 64;                      // NPTS / 128
    const int TRI = NB * (NB + 1) / 2;      // 2080 triangular tiles

    zero_acc_kernel<<<1, 1>>>();
    norms_kernel<<<NPTS / 8, 256>>>(emb);
    gemm_sqdist_kernel<<<TRI, 256>>>(emb);
    topk_curv_kernel<<<NPTS / 8, 256>>>(ref_curv);
    angular_kernel<<<NPTS, 256>>>(emb, ref_ang);
    finalize_kernel<<<1, 1>>>(out);
}

// round 8
// speedup vs baseline: 2.9250x; 1.5224x over previous
#include <cuda_runtime.h>
#include <cuda_bf16.h>
#include <math.h>
#include <stdint.h>

// Problem constants
#define NPTS 8192
#define DIM  512
#define KNN  15
#define KEEP 24     // approx candidates kept per row (margin for bf16 error)
#define NPAIR 105   // 15*14/2
#define FULLM 0xFFFFFFFFu

// ---------------- scratch (device globals: no allocation allowed) -------------
__device__ float  g_sqdist[(size_t)NPTS * NPTS];   // 256 MB approx squared distances
__device__ float  g_norms[NPTS];
__device__ __align__(16) __nv_bfloat16 g_H[(size_t)NPTS * DIM];  // bf16 embeddings
__device__ int    g_knni[NPTS * KNN];
__device__ double g_acc[2];                        // [0]=curv sumsq, [1]=ang sumsq

// ================= PTX helpers (generic sm_80+ only; NO tcgen05) =================
__device__ __forceinline__ uint32_t smem_u32(const void* p) {
    uint32_t a;
    asm("{ .reg .u64 t; cvta.to.shared.u64 t, %1; cvt.u32.u64 %0, t; }" : "=r"(a) : "l"(p));
    return a;
}
__device__ __forceinline__ void cp_async16(uint32_t dst, const void* src) {
    asm volatile("cp.async.cg.shared.global [%0], [%1], 16;" :: "r"(dst), "l"(src));
}
#define CP_COMMIT() asm volatile("cp.async.commit_group;" ::: "memory")

__device__ __forceinline__ void ldmat4(uint32_t* r, uint32_t saddr) {
    asm volatile("ldmatrix.sync.aligned.m8n8.x4.shared.b16 {%0,%1,%2,%3}, [%4];"
                 : "=r"(r[0]), "=r"(r[1]), "=r"(r[2]), "=r"(r[3]) : "r"(saddr));
}
__device__ __forceinline__ void mma_bf16(float* d, const uint32_t* a,
                                         uint32_t b0, uint32_t b1) {
    asm volatile(
        "mma.sync.aligned.m16n8k16.row.col.f32.bf16.bf16.f32 "
        "{%0,%1,%2,%3}, {%4,%5,%6,%7}, {%8,%9}, {%0,%1,%2,%3};"
        : "+f"(d[0]), "+f"(d[1]), "+f"(d[2]), "+f"(d[3])
        : "r"(a[0]), "r"(a[1]), "r"(a[2]), "r"(a[3]), "r"(b0), "r"(b1));
}

// ================= kernel 0: zero accumulators =================
__global__ void zero_acc_kernel() {
    g_acc[0] = 0.0; g_acc[1] = 0.0;
}

// ================= kernel 1: row squared norms (fp32, exact) =================
__global__ void norms_kernel(const float* __restrict__ E) {
    int row  = blockIdx.x * 8 + (threadIdx.x >> 5);
    int lane = threadIdx.x & 31;
    const float4* r = (const float4*)(E + (size_t)row * DIM);
    float s = 0.f;
    #pragma unroll
    for (int c4 = lane; c4 < DIM / 4; c4 += 32) {
        float4 v = r[c4];
        s = fmaf(v.x, v.x, fmaf(v.y, v.y, fmaf(v.z, v.z, fmaf(v.w, v.w, s))));
    }
    #pragma unroll
    for (int o = 16; o; o >>= 1) s += __shfl_xor_sync(FULLM, s, o);
    if (!lane) g_norms[row] = s;
}

// ================= kernel 1b: fp32 -> bf16 =================
__global__ void convert_kernel(const float* __restrict__ E) {
    int idx = blockIdx.x * 256 + threadIdx.x;   // float4 index
    float4 v = ((const float4*)E)[idx];
    __nv_bfloat162 h01 = __floats2bfloat162_rn(v.x, v.y);
    __nv_bfloat162 h23 = __floats2bfloat162_rn(v.z, v.w);
    ((__nv_bfloat162*)g_H)[idx * 2]     = h01;
    ((__nv_bfloat162*)g_H)[idx * 2 + 1] = h23;
}

// ================= kernel 2: bf16 mma.sync Gram -> approx squared distances =====
// CTA tile 128x128, BK=32, 8 warps (2x4), each warp 64x32.
// smem rows padded to 80B -> conflict-free ldmatrix. Double-buffered cp.async.
#define SROW 80
#define TILEB (128 * SROW)      // 10240 bytes per operand tile
#define STAGEB (2 * TILEB)      // A + B per stage

__global__ __launch_bounds__(256, 2) void gemm_bf16_kernel() {
    __shared__ __align__(128) char sbuf[2 * STAGEB];   // 40960 B
    const uint32_t sb = smem_u32(sbuf);
    const int tid  = threadIdx.x;
    const int lane = tid & 31;
    const int wid  = tid >> 5;
    const int row0 = blockIdx.y * 128, col0 = blockIdx.x * 128;
    const int wm = (wid >> 2) * 64;     // warp m offset (0 or 64)
    const int wn = (wid & 3) * 32;      // warp n offset

    float d[4][4][4];
    #pragma unroll
    for (int mt = 0; mt < 4; mt++)
        #pragma unroll
        for (int nt = 0; nt < 4; nt++)
            #pragma unroll
            for (int q = 0; q < 4; q++) d[mt][nt][q] = 0.f;

    const int crow = tid >> 2;          // 0..63
    const int cc   = tid & 3;           // 16B chunk within 64B row

    // prologue: stage 0
    {
        uint32_t a0 = sb, b0 = sb + TILEB;
        #pragma unroll
        for (int j = 0; j < 2; j++) {
            int r = crow + j * 64;
            cp_async16(a0 + r * SROW + cc * 16, &g_H[(size_t)(row0 + r) * DIM + cc * 8]);
            cp_async16(b0 + r * SROW + cc * 16, &g_H[(size_t)(col0 + r) * DIM + cc * 8]);
        }
        CP_COMMIT();
    }

    for (int t = 0; t < 16; t++) {
        if (t < 15) {
            int kk = (t + 1) * 32;
            uint32_t a0 = sb + ((t + 1) & 1) * STAGEB, b0 = a0 + TILEB;
            #pragma unroll
            for (int j = 0; j < 2; j++) {
                int r = crow + j * 64;
                cp_async16(a0 + r * SROW + cc * 16, &g_H[(size_t)(row0 + r) * DIM + kk + cc * 8]);
                cp_async16(b0 + r * SROW + cc * 16, &g_H[(size_t)(col0 + r) * DIM + kk + cc * 8]);
            }
            CP_COMMIT();
            asm volatile("cp.async.wait_group 1;" ::: "memory");
        } else {
            asm volatile("cp.async.wait_group 0;" ::: "memory");
        }
        __syncthreads();

        uint32_t aT = sb + (t & 1) * STAGEB;
        uint32_t bT = aT + TILEB;
        #pragma unroll
        for (int ks = 0; ks < 2; ks++) {
            int kb = ks * 32;   // byte offset of k16 step
            uint32_t aF[4][4], bF[2][4];
            #pragma unroll
            for (int mt = 0; mt < 4; mt++)
                ldmat4(aF[mt], aT + (wm + mt * 16 + (lane & 15)) * SROW + kb + (lane >> 4) * 16);
            #pragma unroll
            for (int g = 0; g < 2; g++)
                ldmat4(bF[g], bT + (wn + g * 16 + (lane & 15)) * SROW + kb + (lane >> 4) * 16);
            #pragma unroll
            for (int mt = 0; mt < 4; mt++)
                #pragma unroll
                for (int nt = 0; nt < 4; nt++)
                    mma_bf16(d[mt][nt], aF[mt], bF[nt >> 1][nt & 1], bF[nt >> 1][(nt & 1) + 2]);
        }
        __syncthreads();
    }

    // epilogue: sq-dist transform + diagonal INF, float2 stores
    const float INF = __int_as_float(0x7f800000);
    #pragma unroll
    for (int mt = 0; mt < 4; mt++) {
        int i0 = row0 + wm + mt * 16 + (lane >> 2);
        int i1 = i0 + 8;
        float n0 = g_norms[i0], n1 = g_norms[i1];
        #pragma unroll
        for (int nt = 0; nt < 4; nt++) {
            int j0 = col0 + wn + nt * 8 + (lane & 3) * 2;
            float ja = g_norms[j0], jb = g_norms[j0 + 1];
            float o00 = fmaxf(n0 + ja - 2.f * d[mt][nt][0], 0.f);
            float o01 = fmaxf(n0 + jb - 2.f * d[mt][nt][1], 0.f);
            float o10 = fmaxf(n1 + ja - 2.f * d[mt][nt][2], 0.f);
            float o11 = fmaxf(n1 + jb - 2.f * d[mt][nt][3], 0.f);
            if (i0 == j0)     o00 = INF;
            if (i0 == j0 + 1) o01 = INF;
            if (i1 == j0)     o10 = INF;
            if (i1 == j0 + 1) o11 = INF;
            *(float2*)&g_sqdist[(size_t)i0 * NPTS + j0] = make_float2(o00, o01);
            *(float2*)&g_sqdist[(size_t)i1 * NPTS + j0] = make_float2(o10, o11);
        }
    }
}

// ================= kernel 3: top-24 approx + exact fp32 rescoring + curvature ===
__global__ __launch_bounds__(256)
void topk_curv_kernel(const float* __restrict__ E, const float* __restrict__ ref_curv) {
    const int row  = blockIdx.x * 8 + (threadIdx.x >> 5);
    const int lane = threadIdx.x & 31;
    const float INF = __int_as_float(0x7f800000);
    const float4* r4 = (const float4*)(g_sqdist + (size_t)row * NPTS);

    // lanes 0..KEEP-1 hold the current KEEP smallest approx values, sorted.
    float lv = INF; int li = 0;
    float T  = INF;

    #pragma unroll 1
    for (int it = 0; it < NPTS / 128; it++) {
        float4 v = r4[it * 32 + lane];
        float m = fminf(fminf(v.x, v.y), fminf(v.z, v.w));
        unsigned ball = __ballot_sync(FULLM, m < T);
        while (ball) {
            int src = __ffs(ball) - 1;
            ball &= ball - 1;
            float w0 = __shfl_sync(FULLM, v.x, src);
            float w1 = __shfl_sync(FULLM, v.y, src);
            float w2 = __shfl_sync(FULLM, v.z, src);
            float w3 = __shfl_sync(FULLM, v.w, src);
            int jb = (it * 32 + src) * 4;
            float wv[4] = {w0, w1, w2, w3};
            #pragma unroll
            for (int c = 0; c < 4; c++) {
                float val = wv[c];
                if (val < T) {                 // warp-uniform
                    unsigned less = __ballot_sync(FULLM, lv < val);
                    int pos = __popc(less);
                    float pv = __shfl_up_sync(FULLM, lv, 1);
                    int   pi = __shfl_up_sync(FULLM, li, 1);
                    if (lane == pos)                      { lv = val; li = jb + c; }
                    else if (lane > pos && lane < KEEP)   { lv = pv;  li = pi;     }
                    T = __shfl_sync(FULLM, lv, KEEP - 1);
                }
            }
        }
    }

    // ---- exact fp32 rescoring of the KEEP candidates ----
    float4 x[4];
    const float4* Xr = (const float4*)&E[(size_t)row * DIM];
    #pragma unroll
    for (int q = 0; q < 4; q++) x[q] = Xr[q * 32 + lane];
    const float ni = g_norms[row];

    float exd = INF;
    #pragma unroll 1
    for (int c = 0; c < KEEP; c++) {
        int idx = __shfl_sync(FULLM, li, c);
        const float4* Y = (const float4*)&E[(size_t)idx * DIM];
        float s = 0.f;
        #pragma unroll
        for (int q = 0; q < 4; q++) {
            float4 y = Y[q * 32 + lane];
            s = fmaf(x[q].x, y.x, fmaf(x[q].y, y.y, fmaf(x[q].z, y.z, fmaf(x[q].w, y.w, s))));
        }
        #pragma unroll
        for (int o = 16; o; o >>= 1) s += __shfl_xor_sync(FULLM, s, o);
        if (lane == c) exd = fmaxf(ni + g_norms[idx] - 2.f * s, 0.f);
    }

    // ---- extract 15 smallest exact values (sorted), with indices ----
    float cur = exd;     // INF for lanes >= KEEP
    float myd = 0.f; int myi = 0;
    #pragma unroll 1
    for (int s = 0; s < KNN; s++) {
        float m = cur; int src = lane;
        #pragma unroll
        for (int o = 16; o; o >>= 1) {
            float om = __shfl_xor_sync(FULLM, m, o);
            int   os = __shfl_xor_sync(FULLM, src, o);
            if (om < m || (om == m && os < src)) { m = om; src = os; }
        }
        int wi = __shfl_sync(FULLM, li, src);
        if (lane == s) { myd = m; myi = wi; }
        if (lane == src) cur = INF;
    }

    // ---- curvature loss (exact, sorted ascending on lanes 0..14) ----
    float dd = (lane < KNN) ? sqrtf(fmaxf(myd, 1e-12f)) : 0.f;
    float ssum = dd;
    #pragma unroll
    for (int o = 16; o; o >>= 1) ssum += __shfl_xor_sync(FULLM, ssum, o);
    float mean = ssum / (float)KNN + 1e-8f;    // EPS_MEAN
    float df = 0.f;
    if (lane < KNN) {
        df = dd / mean - ref_curv[row * KNN + lane];
        g_knni[row * KNN + lane] = myi;
    }
    float l = df * df;
    #pragma unroll
    for (int o = 16; o; o >>= 1) l += __shfl_xor_sync(FULLM, l, o);
    if (lane == 0) atomicAdd(&g_acc[0], (double)l);
}

// ================= kernel 4: angular signature loss =================
__global__ __launch_bounds__(256)
void angular_kernel(const float* __restrict__ E, const float* __restrict__ ref_ang) {
    const int row  = blockIdx.x;
    const int tid  = threadIdx.x;
    const int lane = tid & 31;
    const int w    = tid >> 5;

    __shared__ float ei[DIM];
    __shared__ float vh[KNN][DIM];
    __shared__ float nrm[KNN];
    __shared__ float cosv[128];
    __shared__ float lsum[8];

    if (tid < 128) {
        float4 q = *(const float4*)&E[(size_t)row * DIM + tid * 4];
        *(float4*)&ei[tid * 4] = q;
    }
    if (tid >= 105 && tid < 128) cosv[tid] = __int_as_float(0x7f800000);
    __syncthreads();

    for (int j = w; j < KNN; j += 8) {
        int nb = g_knni[row * KNN + j];
        const float4* src = (const float4*)&E[(size_t)nb * DIM];
        float s = 0.f;
        for (int c4 = lane; c4 < DIM / 4; c4 += 32) {
            float4 q = src[c4];
            float4 e = *(const float4*)&ei[c4 * 4];
            float4 v; v.x = q.x - e.x; v.y = q.y - e.y; v.z = q.z - e.z; v.w = q.w - e.w;
            *(float4*)&vh[j][c4 * 4] = v;
            s = fmaf(v.x, v.x, fmaf(v.y, v.y, fmaf(v.z, v.z, fmaf(v.w, v.w, s))));
        }
        #pragma unroll
        for (int o = 16; o; o >>= 1) s += __shfl_xor_sync(FULLM, s, o);
        if (!lane) nrm[j] = fmaxf(sqrtf(s), 1e-8f);   // EPS_NORM
    }
    __syncthreads();

    for (int p = w; p < NPAIR; p += 8) {
        int jj = 0, rem = p;
        while (rem >= (KNN - 1) - jj) { rem -= (KNN - 1) - jj; jj++; }
        int kk = jj + 1 + rem;
        float s = 0.f;
        for (int c = lane; c < DIM; c += 32)
            s = fmaf(vh[jj][c], vh[kk][c], s);
        #pragma unroll
        for (int o = 16; o; o >>= 1) s += __shfl_xor_sync(FULLM, s, o);
        if (!lane) cosv[p] = s / (nrm[jj] * nrm[kk]);
    }
    __syncthreads();

    for (int k = 2; k <= 128; k <<= 1) {
        for (int j2 = k >> 1; j2 > 0; j2 >>= 1) {
            if (tid < 128) {
                int ixj = tid ^ j2;
                if (ixj > tid) {
                    float a = cosv[tid], b = cosv[ixj];
                    bool up = ((tid & k) == 0);
                    if ((a > b) == up) { cosv[tid] = b; cosv[ixj] = a; }
                }
            }
            __syncthreads();
        }
    }

    float s = 0.f;
    for (int t2 = tid; t2 < NPAIR; t2 += 256) {
        float df = cosv[t2] - ref_ang[(size_t)row * NPAIR + t2];
        s = fmaf(df, df, s);
    }
    #pragma unroll
    for (int o = 16; o; o >>= 1) s += __shfl_xor_sync(FULLM, s, o);
    if (!lane) lsum[w] = s;
    __syncthreads();
    if (tid == 0) {
        float t2 = 0.f;
        #pragma unroll
        for (int q = 0; q < 8; q++) t2 += lsum[q];
        atomicAdd(&g_acc[1], (double)t2);
    }
}

// ================= kernel 5: finalize =================
__global__ void finalize_kernel(float* out) {
    double curv = g_acc[0] / ((double)NPTS * KNN);
    double ang  = g_acc[1] / ((double)NPTS * NPAIR);
    out[0] = (float)(0.3 * curv + 0.7 * ang);
}

// ================= launch =================
extern "C" void kernel_launch(void* const* d_in, const int* in_sizes, int n_in,
                              void* d_out, int out_size) {
    const float* emb      = (const float*)d_in[0];
    const float* ref_curv = (const float*)d_in[1];
    const float* ref_ang  = (const float*)d_in[2];
    float* out = (float*)d_out;

    zero_acc_kernel<<<1, 1>>>();
    norms_kernel<<<NPTS / 8, 256>>>(emb);
    convert_kernel<<<NPTS * DIM / 4 / 256, 256>>>(emb);
    gemm_bf16_kernel<<<dim3(NPTS / 128, NPTS / 128), 256>>>();
    topk_curv_kernel<<<NPTS / 8, 256>>>(emb, ref_curv);
    angular_kernel<<<NPTS, 256>>>(emb, ref_ang);
    finalize_kernel<<<1, 1>>>(out);
}

// round 11
// speedup vs baseline: 3.7072x; 1.2674x over previous
#include <cuda_runtime.h>
#include <cuda_bf16.h>
#include <cuda_fp16.h>
#include <math.h>
#include <stdint.h>

// Problem constants
#define NPTS 8192
#define DIM  512
#define KNN  15
#define KEEP 24     // approx candidates kept per row (margin for bf16+fp16 error)
#define NPAIR 105   // 15*14/2
#define FULLM 0xFFFFFFFFu

// ---------------- scratch (device globals: no allocation allowed) -------------
__device__ __align__(16) __half g_sqd[(size_t)NPTS * NPTS];      // 128 MB approx sq dists
__device__ float  g_norms[NPTS];
__device__ __align__(16) __nv_bfloat16 g_H[(size_t)NPTS * DIM];  // bf16 embeddings
__device__ int    g_knni[NPTS * KNN];
__device__ double g_acc[2];                        // [0]=curv sumsq, [1]=ang sumsq

// ================= PTX helpers (generic sm_80+ only; NO tcgen05) =================
__device__ __forceinline__ uint32_t smem_u32(const void* p) {
    uint32_t a;
    asm("{ .reg .u64 t; cvta.to.shared.u64 t, %1; cvt.u32.u64 %0, t; }" : "=r"(a) : "l"(p));
    return a;
}
__device__ __forceinline__ void cp_async16(uint32_t dst, const void* src) {
    asm volatile("cp.async.cg.shared.global [%0], [%1], 16;" :: "r"(dst), "l"(src));
}
#define CP_COMMIT() asm volatile("cp.async.commit_group;" ::: "memory")

__device__ __forceinline__ void ldmat4(uint32_t* r, uint32_t saddr) {
    asm volatile("ldmatrix.sync.aligned.m8n8.x4.shared.b16 {%0,%1,%2,%3}, [%4];"
                 : "=r"(r[0]), "=r"(r[1]), "=r"(r[2]), "=r"(r[3]) : "r"(saddr));
}
__device__ __forceinline__ void mma_bf16(float* d, const uint32_t* a,
                                         uint32_t b0, uint32_t b1) {
    asm volatile(
        "mma.sync.aligned.m16n8k16.row.col.f32.bf16.bf16.f32 "
        "{%0,%1,%2,%3}, {%4,%5,%6,%7}, {%8,%9}, {%0,%1,%2,%3};"
        : "+f"(d[0]), "+f"(d[1]), "+f"(d[2]), "+f"(d[3])
        : "r"(a[0]), "r"(a[1]), "r"(a[2]), "r"(a[3]), "r"(b0), "r"(b1));
}

// ================= kernel 0: zero accumulators =================
__global__ void zero_acc_kernel() {
    g_acc[0] = 0.0; g_acc[1] = 0.0;
}

// ================= kernel 1: row squared norms (fp32, exact) =================
__global__ void norms_kernel(const float* __restrict__ E) {
    int row  = blockIdx.x * 8 + (threadIdx.x >> 5);
    int lane = threadIdx.x & 31;
    const float4* r = (const float4*)(E + (size_t)row * DIM);
    float s = 0.f;
    #pragma unroll
    for (int c4 = lane; c4 < DIM / 4; c4 += 32) {
        float4 v = r[c4];
        s = fmaf(v.x, v.x, fmaf(v.y, v.y, fmaf(v.z, v.z, fmaf(v.w, v.w, s))));
    }
    #pragma unroll
    for (int o = 16; o; o >>= 1) s += __shfl_xor_sync(FULLM, s, o);
    if (!lane) g_norms[row] = s;
}

// ================= kernel 1b: fp32 -> bf16 =================
__global__ void convert_kernel(const float* __restrict__ E) {
    int idx = blockIdx.x * 256 + threadIdx.x;   // float4 index
    float4 v = ((const float4*)E)[idx];
    __nv_bfloat162 h01 = __floats2bfloat162_rn(v.x, v.y);
    __nv_bfloat162 h23 = __floats2bfloat162_rn(v.z, v.w);
    ((__nv_bfloat162*)g_H)[idx * 2]     = h01;
    ((__nv_bfloat162*)g_H)[idx * 2 + 1] = h23;
}

// ================= kernel 2: bf16 mma.sync Gram -> approx sq dists (fp16) =======
// Triangular grid (bx<=by). CTA tile 128x128, BK=32, 8 warps, each 64x32.
// smem rows padded to 80B -> conflict-free ldmatrix. Double-buffered cp.async.
// Mirror tiles written via smem transpose staging (coalesced 256B rows).
#define SROW 80
#define TILEB (128 * SROW)      // 10240 bytes per operand tile
#define STAGEB (2 * TILEB)      // A + B per stage
#define MIR_STRIDE 136          // halves; 272B row, 16B aligned

__global__ __launch_bounds__(256, 2) void gemm_bf16_kernel() {
    __shared__ __align__(128) char sbuf[2 * STAGEB];   // 40960 B (reused for mirror)
    const uint32_t sb = smem_u32(sbuf);
    const int tid  = threadIdx.x;
    const int lane = tid & 31;
    const int wid  = tid >> 5;

    // triangular decode: bx <= by
    int t = blockIdx.x;
    int by = (int)((sqrtf(8.0f * (float)t + 1.0f) - 1.0f) * 0.5f);
    while ((by + 1) * (by + 2) / 2 <= t) ++by;
    while (by * (by + 1) / 2 > t) --by;
    int bx = t - by * (by + 1) / 2;

    const int row0 = by * 128, col0 = bx * 128;
    const int wm = (wid >> 2) * 64;     // warp m offset (0 or 64)
    const int wn = (wid & 3) * 32;      // warp n offset

    float d[4][4][4];
    #pragma unroll
    for (int mt = 0; mt < 4; mt++)
        #pragma unroll
        for (int nt = 0; nt < 4; nt++)
            #pragma unroll
            for (int q = 0; q < 4; q++) d[mt][nt][q] = 0.f;

    const int crow = tid >> 2;          // 0..63
    const int cc   = tid & 3;           // 16B chunk within 64B row

    // prologue: stage 0
    {
        uint32_t a0 = sb, b0 = sb + TILEB;
        #pragma unroll
        for (int j = 0; j < 2; j++) {
            int r = crow + j * 64;
            cp_async16(a0 + r * SROW + cc * 16, &g_H[(size_t)(row0 + r) * DIM + cc * 8]);
            cp_async16(b0 + r * SROW + cc * 16, &g_H[(size_t)(col0 + r) * DIM + cc * 8]);
        }
        CP_COMMIT();
    }

    for (int t2 = 0; t2 < 16; t2++) {
        if (t2 < 15) {
            int kk = (t2 + 1) * 32;
            uint32_t a0 = sb + ((t2 + 1) & 1) * STAGEB, b0 = a0 + TILEB;
            #pragma unroll
            for (int j = 0; j < 2; j++) {
                int r = crow + j * 64;
                cp_async16(a0 + r * SROW + cc * 16, &g_H[(size_t)(row0 + r) * DIM + kk + cc * 8]);
                cp_async16(b0 + r * SROW + cc * 16, &g_H[(size_t)(col0 + r) * DIM + kk + cc * 8]);
            }
            CP_COMMIT();
            asm volatile("cp.async.wait_group 1;" ::: "memory");
        } else {
            asm volatile("cp.async.wait_group 0;" ::: "memory");
        }
        __syncthreads();

        uint32_t aT = sb + (t2 & 1) * STAGEB;
        uint32_t bT = aT + TILEB;
        #pragma unroll
        for (int ks = 0; ks < 2; ks++) {
            int kb = ks * 32;   // byte offset of k16 step
            uint32_t aF[4][4], bF[2][4];
            #pragma unroll
            for (int mt = 0; mt < 4; mt++)
                ldmat4(aF[mt], aT + (wm + mt * 16 + (lane & 15)) * SROW + kb + (lane >> 4) * 16);
            #pragma unroll
            for (int g = 0; g < 2; g++)
                ldmat4(bF[g], bT + (wn + g * 16 + (lane & 15)) * SROW + kb + (lane >> 4) * 16);
            #pragma unroll
            for (int mt = 0; mt < 4; mt++)
                #pragma unroll
                for (int nt = 0; nt < 4; nt++)
                    mma_bf16(d[mt][nt], aF[mt], bF[nt >> 1][nt & 1], bF[nt >> 1][(nt & 1) + 2]);
        }
        __syncthreads();
    }

    // ---------------- epilogue: sq-dist (fp16) ----------------
    const float INF = __int_as_float(0x7f800000);
    float sv[4][4][4];
    #pragma unroll
    for (int mt = 0; mt < 4; mt++) {
        int i0 = row0 + wm + mt * 16 + (lane >> 2);
        int i1 = i0 + 8;
        float n0 = g_norms[i0], n1 = g_norms[i1];
        #pragma unroll
        for (int nt = 0; nt < 4; nt++) {
            int j0 = col0 + wn + nt * 8 + (lane & 3) * 2;
            float ja = g_norms[j0], jb = g_norms[j0 + 1];
            float o00 = fmaxf(n0 + ja - 2.f * d[mt][nt][0], 0.f);
            float o01 = fmaxf(n0 + jb - 2.f * d[mt][nt][1], 0.f);
            float o10 = fmaxf(n1 + ja - 2.f * d[mt][nt][2], 0.f);
            float o11 = fmaxf(n1 + jb - 2.f * d[mt][nt][3], 0.f);
            if (i0 == j0)     o00 = INF;
            if (i0 == j0 + 1) o01 = INF;
            if (i1 == j0)     o10 = INF;
            if (i1 == j0 + 1) o11 = INF;
            sv[mt][nt][0] = o00; sv[mt][nt][1] = o01;
            sv[mt][nt][2] = o10; sv[mt][nt][3] = o11;
            // direct store (lower triangle orientation)
            *(__half2*)&g_sqd[(size_t)i0 * NPTS + j0] = __floats2half2_rn(o00, o01);
            *(__half2*)&g_sqd[(size_t)i1 * NPTS + j0] = __floats2half2_rn(o10, o11);
        }
    }

    // mirror via smem transpose staging (only off-diagonal tiles)
    if (bx < by) {
        __half* S = (__half*)sbuf;     // [128][MIR_STRIDE]
        #pragma unroll
        for (int mt = 0; mt < 4; mt++) {
            int il0 = wm + mt * 16 + (lane >> 2);
            int il1 = il0 + 8;
            #pragma unroll
            for (int nt = 0; nt < 4; nt++) {
                int jl0 = wn + nt * 8 + (lane & 3) * 2;
                S[(jl0)     * MIR_STRIDE + il0] = __float2half_rn(sv[mt][nt][0]);
                S[(jl0 + 1) * MIR_STRIDE + il0] = __float2half_rn(sv[mt][nt][1]);
                S[(jl0)     * MIR_STRIDE + il1] = __float2half_rn(sv[mt][nt][2]);
                S[(jl0 + 1) * MIR_STRIDE + il1] = __float2half_rn(sv[mt][nt][3]);
            }
        }
        __syncthreads();
        // stream out: row jl of mirror tile -> g_sqd[(col0+jl)*NPTS + row0 ..+128)
        int jl = tid >> 1;
        int cb = (tid & 1) * 8;
        uint4* dst = (uint4*)&g_sqd[(size_t)(col0 + jl) * NPTS + row0];
        const uint4* srcp = (const uint4*)&S[jl * MIR_STRIDE];
        #pragma unroll
        for (int c = 0; c < 8; c++)
            dst[cb + c] = srcp[cb + c];
    }
}

// ================= kernel 3: top-24 approx (fp16 scan) + exact rescoring ========
__global__ __launch_bounds__(256)
void topk_curv_kernel(const float* __restrict__ E, const float* __restrict__ ref_curv) {
    const int row  = blockIdx.x * 8 + (threadIdx.x >> 5);
    const int lane = threadIdx.x & 31;
    const float INF = __int_as_float(0x7f800000);
    const uint4* r8 = (const uint4*)(g_sqd + (size_t)row * NPTS);

    // lanes 0..KEEP-1 hold the current KEEP smallest approx values, sorted.
    float lv = INF; int li = 0;
    float T  = INF;

    #pragma unroll 1
    for (int it = 0; it < NPTS / 256; it++) {
        uint4 v = r8[it * 32 + lane];
        const __half2* hp = (const __half2*)&v;
        float2 f0 = __half22float2(hp[0]);
        float2 f1 = __half22float2(hp[1]);
        float2 f2 = __half22float2(hp[2]);
        float2 f3 = __half22float2(hp[3]);
        float m = fminf(fminf(fminf(f0.x, f0.y), fminf(f1.x, f1.y)),
                        fminf(fminf(f2.x, f2.y), fminf(f3.x, f3.y)));
        unsigned ball = __ballot_sync(FULLM, m < T);
        while (ball) {
            int src = __ffs(ball) - 1;
            ball &= ball - 1;
            uint32_t w0 = __shfl_sync(FULLM, v.x, src);
            uint32_t w1 = __shfl_sync(FULLM, v.y, src);
            uint32_t w2 = __shfl_sync(FULLM, v.z, src);
            uint32_t w3 = __shfl_sync(FULLM, v.w, src);
            int jb = (it * 32 + src) * 8;
            uint32_t ww[4] = {w0, w1, w2, w3};
            #pragma unroll
            for (int h = 0; h < 4; h++) {
                float2 fp = __half22float2(*(const __half2*)&ww[h]);
                float pv2[2] = {fp.x, fp.y};
                #pragma unroll
                for (int c = 0; c < 2; c++) {
                    float val = pv2[c];
                    if (val < T) {                 // warp-uniform
                        unsigned less = __ballot_sync(FULLM, lv < val);
                        int pos = __popc(less);
                        float pv = __shfl_up_sync(FULLM, lv, 1);
                        int   pi = __shfl_up_sync(FULLM, li, 1);
                        if (lane == pos)                      { lv = val; li = jb + h * 2 + c; }
                        else if (lane > pos && lane < KEEP)   { lv = pv;  li = pi;             }
                        T = __shfl_sync(FULLM, lv, KEEP - 1);
                    }
                }
            }
        }
    }

    // ---- exact fp32 rescoring of the KEEP candidates ----
    float4 x[4];
    const float4* Xr = (const float4*)&E[(size_t)row * DIM];
    #pragma unroll
    for (int q = 0; q < 4; q++) x[q] = Xr[q * 32 + lane];
    const float ni = g_norms[row];

    float exd = INF;
    #pragma unroll 1
    for (int c = 0; c < KEEP; c++) {
        int idx = __shfl_sync(FULLM, li, c);
        const float4* Y = (const float4*)&E[(size_t)idx * DIM];
        float s = 0.f;
        #pragma unroll
        for (int q = 0; q < 4; q++) {
            float4 y = Y[q * 32 + lane];
            s = fmaf(x[q].x, y.x, fmaf(x[q].y, y.y, fmaf(x[q].z, y.z, fmaf(x[q].w, y.w, s))));
        }
        #pragma unroll
        for (int o = 16; o; o >>= 1) s += __shfl_xor_sync(FULLM, s, o);
        if (lane == c) exd = fmaxf(ni + g_norms[idx] - 2.f * s, 0.f);
    }

    // ---- extract 15 smallest exact values (sorted), with indices ----
    float cur = exd;     // INF for lanes >= KEEP
    float myd = 0.f; int myi = 0;
    #pragma unroll 1
    for (int s = 0; s < KNN; s++) {
        float m = cur; int src = lane;
        #pragma unroll
        for (int o = 16; o; o >>= 1) {
            float om = __shfl_xor_sync(FULLM, m, o);
            int   os = __shfl_xor_sync(FULLM, src, o);
            if (om < m || (om == m && os < src)) { m = om; src = os; }
        }
        int wi = __shfl_sync(FULLM, li, src);
        if (lane == s) { myd = m; myi = wi; }
        if (lane == src) cur = INF;
    }

    // ---- curvature loss (exact, sorted ascending on lanes 0..14) ----
    float dd = (lane < KNN) ? sqrtf(fmaxf(myd, 1e-12f)) : 0.f;
    float ssum = dd;
    #pragma unroll
    for (int o = 16; o; o >>= 1) ssum += __shfl_xor_sync(FULLM, ssum, o);
    float mean = ssum / (float)KNN + 1e-8f;    // EPS_MEAN
    float df = 0.f;
    if (lane < KNN) {
        df = dd / mean - ref_curv[row * KNN + lane];
        g_knni[row * KNN + lane] = myi;
    }
    float l = df * df;
    #pragma unroll
    for (int o = 16; o; o >>= 1) l += __shfl_xor_sync(FULLM, l, o);
    if (lane == 0) atomicAdd(&g_acc[0], (double)l);
}

// ================= kernel 4: angular signature loss =================
__global__ __launch_bounds__(256)
void angular_kernel(const float* __restrict__ E, const float* __restrict__ ref_ang) {
    const int row  = blockIdx.x;
    const int tid  = threadIdx.x;
    const int lane = tid & 31;
    const int w    = tid >> 5;

    __shared__ float ei[DIM];
    __shared__ float vh[KNN][DIM];
    __shared__ float nrm[KNN];
    __shared__ float cosv[128];
    __shared__ float lsum[8];

    if (tid < 128) {
        float4 q = *(const float4*)&E[(size_t)row * DIM + tid * 4];
        *(float4*)&ei[tid * 4] = q;
    }
    if (tid >= 105 && tid < 128) cosv[tid] = __int_as_float(0x7f800000);
    __syncthreads();

    for (int j = w; j < KNN; j += 8) {
        int nb = g_knni[row * KNN + j];
        const float4* src = (const float4*)&E[(size_t)nb * DIM];
        float s = 0.f;
        for (int c4 = lane; c4 < DIM / 4; c4 += 32) {
            float4 q = src[c4];
            float4 e = *(const float4*)&ei[c4 * 4];
            float4 v; v.x = q.x - e.x; v.y = q.y - e.y; v.z = q.z - e.z; v.w = q.w - e.w;
            *(float4*)&vh[j][c4 * 4] = v;
            s = fmaf(v.x, v.x, fmaf(v.y, v.y, fmaf(v.z, v.z, fmaf(v.w, v.w, s))));
        }
        #pragma unroll
        for (int o = 16; o; o >>= 1) s += __shfl_xor_sync(FULLM, s, o);
        if (!lane) nrm[j] = fmaxf(sqrtf(s), 1e-8f);   // EPS_NORM
    }
    __syncthreads();

    for (int p = w; p < NPAIR; p += 8) {
        int jj = 0, rem = p;
        while (rem >= (KNN - 1) - jj) { rem -= (KNN - 1) - jj; jj++; }
        int kk = jj + 1 + rem;
        float s = 0.f;
        for (int c = lane; c < DIM; c += 32)
            s = fmaf(vh[jj][c], vh[kk][c], s);
        #pragma unroll
        for (int o = 16; o; o >>= 1) s += __shfl_xor_sync(FULLM, s, o);
        if (!lane) cosv[p] = s / (nrm[jj] * nrm[kk]);
    }
    __syncthreads();

    for (int k = 2; k <= 128; k <<= 1) {
        for (int j2 = k >> 1; j2 > 0; j2 >>= 1) {
            if (tid < 128) {
                int ixj = tid ^ j2;
                if (ixj > tid) {
                    float a = cosv[tid], b = cosv[ixj];
                    bool up = ((tid & k) == 0);
                    if ((a > b) == up) { cosv[tid] = b; cosv[ixj] = a; }
                }
            }
            __syncthreads();
        }
    }

    float s = 0.f;
    for (int t2 = tid; t2 < NPAIR; t2 += 256) {
        float df = cosv[t2] - ref_ang[(size_t)row * NPAIR + t2];
        s = fmaf(df, df, s);
    }
    #pragma unroll
    for (int o = 16; o; o >>= 1) s += __shfl_xor_sync(FULLM, s, o);
    if (!lane) lsum[w] = s;
    __syncthreads();
    if (tid == 0) {
        float t2 = 0.f;
        #pragma unroll
        for (int q = 0; q < 8; q++) t2 += lsum[q];
        atomicAdd(&g_acc[1], (double)t2);
    }
}

// ================= kernel 5: finalize =================
__global__ void finalize_kernel(float* out) {
    double curv = g_acc[0] / ((double)NPTS * KNN);
    double ang  = g_acc[1] / ((double)NPTS * NPAIR);
    out[0] = (float)(0.3 * curv + 0.7 * ang);
}

// ================= launch =================
extern "C" void kernel_launch(void* const* d_in, const int* in_sizes, int n_in,
                              void* d_out, int out_size) {
    const float* emb      = (const float*)d_in[0];
    const float* ref_curv = (const float*)d_in[1];
    const float* ref_ang  = (const float*)d_in[2];
    float* out = (float*)d_out;

    const int NB = 64;                      // NPTS / 128
    const int TRI = NB * (NB + 1) / 2;      // 2080 triangular tiles

    zero_acc_kernel<<<1, 1>>>();
    norms_kernel<<<NPTS / 8, 256>>>(emb);
    convert_kernel<<<NPTS * DIM / 4 / 256, 256>>>(emb);
    gemm_bf16_kernel<<<TRI, 256>>>();
    topk_curv_kernel<<<NPTS / 8, 256>>>(emb, ref_curv);
    angular_kernel<<<NPTS, 256>>>(emb, ref_ang);
    finalize_kernel<<<1, 1>>>(out);
}